// round 1
// baseline (speedup 1.0000x reference)
#include <cuda_runtime.h>
#include <cuda_bf16.h>
#include <math.h>

// ---------------- model dims ----------------
#define DD   768
#define HH   12
#define HDIM 64
#define DFF  3072
#define VV   32000
#define SS   2048
#define EPS  1e-5f

// ---------------- scratch (no allocs allowed) ----------------
__device__ float g_x   [SS * DD];        // embed out / ln2 out
__device__ float g_qkv [SS * 3 * DD];
__device__ float g_o   [SS * DD];        // attention out
__device__ float g_proj[SS * DD];        // out-proj result
__device__ float g_ln1 [SS * DD];        // first LN out (ffn input + residual)
__device__ float g_f1  [SS * DFF];       // gelu(ffn1)
__device__ float g_f2  [SS * DD];        // ffn2 result

// ---------------- embed ----------------
__global__ void embed_kernel(const int* __restrict__ ids,
                             const float* __restrict__ ew,
                             const float* __restrict__ pe,
                             float* __restrict__ x)
{
    int i = blockIdx.x * 256 + threadIdx.x;   // over SS*DD
    if (i >= SS * DD) return;
    int s = i / DD, d = i - s * DD;
    x[i] = ew[ids[s] * DD + d] * 27.712812921102035f + pe[i];
}

// ---------------- generic SGEMM: C[M,N] = A[M,K] @ Bt[N,K]^T + bias, opt GELU ----------------
// BM=BN=128, BK=16, 256 threads, 8x8 per thread. Requires M%128==0, N%128==0, K%16==0.
__global__ __launch_bounds__(256)
void gemm_kernel(const float* __restrict__ A, const float* __restrict__ Bt,
                 const float* __restrict__ bias, float* __restrict__ C,
                 int M, int N, int K, int act)
{
    constexpr int BM = 128, BN = 128, BK = 16, TM = 8, TN = 8;
    __shared__ float As[BK][BM];
    __shared__ float Bs[BK][BN];

    const int tid = threadIdx.x;
    const int m0 = blockIdx.y * BM;
    const int n0 = blockIdx.x * BN;
    const int tx = tid & 15;        // 16 col groups
    const int ty = tid >> 4;        // 16 row groups

    float acc[TM][TN];
#pragma unroll
    for (int i = 0; i < TM; i++)
#pragma unroll
        for (int j = 0; j < TN; j++) acc[i][j] = 0.f;

    const float* Ab = A  + (size_t)m0 * K;
    const float* Bb = Bt + (size_t)n0 * K;

    for (int k0 = 0; k0 < K; k0 += BK) {
        // each thread loads 2 float4 from A-tile and 2 from B-tile
#pragma unroll
        for (int r = 0; r < 2; r++) {
            int id  = tid + r * 256;       // 0..511 float4 slots
            int row = id >> 2;             // 0..127
            int c4  = (id & 3) << 2;       // 0,4,8,12
            float4 av = *reinterpret_cast<const float4*>(Ab + (size_t)row * K + k0 + c4);
            As[c4 + 0][row] = av.x; As[c4 + 1][row] = av.y;
            As[c4 + 2][row] = av.z; As[c4 + 3][row] = av.w;
            float4 bv = *reinterpret_cast<const float4*>(Bb + (size_t)row * K + k0 + c4);
            Bs[c4 + 0][row] = bv.x; Bs[c4 + 1][row] = bv.y;
            Bs[c4 + 2][row] = bv.z; Bs[c4 + 3][row] = bv.w;
        }
        __syncthreads();
#pragma unroll
        for (int k = 0; k < BK; k++) {
            float ar[TM], br[TN];
#pragma unroll
            for (int i = 0; i < TM; i++) ar[i] = As[k][ty * TM + i];
#pragma unroll
            for (int j = 0; j < TN; j++) br[j] = Bs[k][tx * TN + j];
#pragma unroll
            for (int i = 0; i < TM; i++)
#pragma unroll
                for (int j = 0; j < TN; j++) acc[i][j] += ar[i] * br[j];
        }
        __syncthreads();
    }

#pragma unroll
    for (int i = 0; i < TM; i++) {
        int m = m0 + ty * TM + i;
        float* Cr = C + (size_t)m * N + n0 + tx * TN;
#pragma unroll
        for (int j = 0; j < TN; j++) {
            float v = acc[i][j];
            if (bias) v += bias[n0 + tx * TN + j];
            if (act) v = 0.5f * v * (1.f + erff(v * 0.70710678118654752f));
            Cr[j] = v;
        }
    }
}

// ---------------- causal flash attention ----------------
// grid (SS/128, HH), 128 threads, one query row per thread.
__global__ __launch_bounds__(128)
void attn_kernel(const float* __restrict__ qkv, float* __restrict__ o)
{
    __shared__ float Ks[64][64];
    __shared__ float Vs[64][64];

    const int h = blockIdx.y;
    const int tid = threadIdx.x;
    const int q_idx = blockIdx.x * 128 + tid;
    const int q_blk_end = blockIdx.x * 128 + 127;

    float q[HDIM];
    const float* qrow = qkv + (size_t)q_idx * (3 * DD) + h * HDIM;
#pragma unroll
    for (int d = 0; d < HDIM; d++) q[d] = qrow[d];

    float m = -1e30f, l = 0.f;
    float acc[HDIM];
#pragma unroll
    for (int d = 0; d < HDIM; d++) acc[d] = 0.f;

    const float scale = 0.125f;   // 1/sqrt(64)

    for (int kt = 0; kt * 64 <= q_blk_end; kt++) {
        // cooperative load of 64x64 K and V tiles (float4)
#pragma unroll
        for (int r = 0; r < 8; r++) {
            int id  = tid + r * 128;     // 0..1023 float4 slots
            int row = id >> 4;           // 0..63
            int c4  = (id & 15) << 2;    // 0..60
            const float* base = qkv + (size_t)(kt * 64 + row) * (3 * DD) + h * HDIM + c4;
            *reinterpret_cast<float4*>(&Ks[row][c4]) =
                *reinterpret_cast<const float4*>(base + DD);
            *reinterpret_cast<float4*>(&Vs[row][c4]) =
                *reinterpret_cast<const float4*>(base + 2 * DD);
        }
        __syncthreads();

        int jmax = q_idx - kt * 64;
        if (jmax > 63) jmax = 63;
        for (int j = 0; j <= jmax; j++) {
            float s = 0.f;
#pragma unroll
            for (int d = 0; d < HDIM; d++) s += q[d] * Ks[j][d];
            s *= scale;
            float mnew = fmaxf(m, s);
            float corr = __expf(m - mnew);
            float p    = __expf(s - mnew);
            l = l * corr + p;
#pragma unroll
            for (int d = 0; d < HDIM; d++) acc[d] = acc[d] * corr + p * Vs[j][d];
            m = mnew;
        }
        __syncthreads();
    }

    float inv = 1.f / l;
    float* orow = o + (size_t)q_idx * DD + h * HDIM;
#pragma unroll
    for (int d = 0; d < HDIM; d++) orow[d] = acc[d] * inv;
}

// ---------------- add + LayerNorm ----------------
__device__ __forceinline__ float warp_sum(float v)
{
#pragma unroll
    for (int o = 16; o > 0; o >>= 1) v += __shfl_xor_sync(0xffffffffu, v, o);
    return v;
}

__global__ __launch_bounds__(256)
void add_ln_kernel(const float* __restrict__ x, const float* __restrict__ y,
                   const float* __restrict__ g, const float* __restrict__ b,
                   float* __restrict__ out)
{
    __shared__ float buf[DD];
    __shared__ float red[8];
    const int row = blockIdx.x;
    const int tid = threadIdx.x;
    const int wid = tid >> 5, lane = tid & 31;

    float local = 0.f;
    for (int d = tid; d < DD; d += 256) {
        float v = x[(size_t)row * DD + d] + y[(size_t)row * DD + d];
        buf[d] = v;
        local += v;
    }
    local = warp_sum(local);
    if (lane == 0) red[wid] = local;
    __syncthreads();
    float tot = (lane < 8) ? red[lane] : 0.f;
    tot = warp_sum(tot);
    float mu = __shfl_sync(0xffffffffu, tot, 0) * (1.f / DD);

    float lv = 0.f;
    for (int d = tid; d < DD; d += 256) {
        float t = buf[d] - mu;
        lv += t * t;
    }
    lv = warp_sum(lv);
    __syncthreads();
    if (lane == 0) red[wid] = lv;
    __syncthreads();
    float tv = (lane < 8) ? red[lane] : 0.f;
    tv = warp_sum(tv);
    float rstd = rsqrtf(__shfl_sync(0xffffffffu, tv, 0) * (1.f / DD) + EPS);

    for (int d = tid; d < DD; d += 256)
        out[(size_t)row * DD + d] = (buf[d] - mu) * rstd * g[d] + b[d];
}

// ---------------- launch ----------------
extern "C" void kernel_launch(void* const* d_in, const int* in_sizes, int n_in,
                              void* d_out, int out_size)
{
    const int*   ids   = (const int*)  d_in[0];
    const float* ew    = (const float*)d_in[1];
    const float* pe    = (const float*)d_in[2];
    const float* inw   = (const float*)d_in[3];
    const float* inb   = (const float*)d_in[4];
    const float* ow    = (const float*)d_in[5];
    const float* ob    = (const float*)d_in[6];
    const float* ng    = (const float*)d_in[7];
    const float* nb    = (const float*)d_in[8];
    const float* w1    = (const float*)d_in[9];
    const float* b1    = (const float*)d_in[10];
    const float* w2    = (const float*)d_in[11];
    const float* b2    = (const float*)d_in[12];
    const float* lmw   = (const float*)d_in[13];
    float* out = (float*)d_out;

    float *x, *qkv, *o, *proj, *ln1, *f1, *f2;
    cudaGetSymbolAddress((void**)&x,    g_x);
    cudaGetSymbolAddress((void**)&qkv,  g_qkv);
    cudaGetSymbolAddress((void**)&o,    g_o);
    cudaGetSymbolAddress((void**)&proj, g_proj);
    cudaGetSymbolAddress((void**)&ln1,  g_ln1);
    cudaGetSymbolAddress((void**)&f1,   g_f1);
    cudaGetSymbolAddress((void**)&f2,   g_f2);

    // 1. embed
    embed_kernel<<<(SS * DD + 255) / 256, 256>>>(ids, ew, pe, x);

    // 2. qkv = x @ in_proj_w^T + b      [2048, 2304]
    gemm_kernel<<<dim3((3 * DD) / 128, SS / 128), 256>>>(x, inw, inb, qkv, SS, 3 * DD, DD, 0);

    // 3. attention
    attn_kernel<<<dim3(SS / 128, HH), 128>>>(qkv, o);

    // 4. out proj                       [2048, 768]
    gemm_kernel<<<dim3(DD / 128, SS / 128), 256>>>(o, ow, ob, proj, SS, DD, DD, 0);

    // 5. ln1 = LN(x + proj)
    add_ln_kernel<<<SS, 256>>>(x, proj, ng, nb, ln1);

    // 6. f1 = gelu(ln1 @ w1^T + b1)     [2048, 3072]
    gemm_kernel<<<dim3(DFF / 128, SS / 128), 256>>>(ln1, w1, b1, f1, SS, DFF, DD, 1);

    // 7. f2 = f1 @ w2^T + b2            [2048, 768]
    gemm_kernel<<<dim3(DD / 128, SS / 128), 256>>>(f1, w2, b2, f2, SS, DD, DFF, 0);

    // 8. x = LN(ln1 + f2)
    add_ln_kernel<<<SS, 256>>>(ln1, f2, ng, nb, x);

    // 9. logits = x @ lm_head_w^T       [2048, 32000]
    gemm_kernel<<<dim3(VV / 128, SS / 128), 256>>>(x, lmw, nullptr, out, SS, VV, DD, 0);
}

// round 4
// speedup vs baseline: 2.2458x; 2.2458x over previous
#include <cuda_runtime.h>
#include <cuda_bf16.h>
#include <math.h>
#include <stdint.h>

// ---------------- model dims ----------------
#define DD   768
#define HH   12
#define HDIM 64
#define DFF  3072
#define VV   32000
#define SS   2048
#define EPS  1e-5f

typedef __nv_bfloat16 bf16;

// ---------------- scratch (no allocs allowed) ----------------
__device__ float g_x   [SS * DD];
__device__ float g_qkv [SS * 3 * DD];
__device__ float g_proj[SS * DD];
__device__ float g_ln1 [SS * DD];
__device__ float g_f2  [SS * DD];

__device__ bf16 g_xh [SS * DD],  g_xl [SS * DD];
__device__ bf16 g_oh [SS * DD],  g_ol [SS * DD];
__device__ bf16 g_l1h[SS * DD],  g_l1l[SS * DD];
__device__ bf16 g_f1h[SS * DFF], g_f1l[SS * DFF];
__device__ bf16 g_x2h[SS * DD],  g_x2l[SS * DD];

__device__ bf16 g_wih[3 * DD * DD], g_wil[3 * DD * DD];
__device__ bf16 g_woh[DD * DD],     g_wol[DD * DD];
__device__ bf16 g_w1h[DFF * DD],    g_w1l[DFF * DD];
__device__ bf16 g_w2h[DD * DFF],    g_w2l[DD * DFF];
__device__ bf16 g_lmh[VV * DD],     g_lml[VV * DD];

// ---------------- helpers ----------------
__device__ __forceinline__ uint32_t smem_u32(const void* p) {
    uint32_t a;
    asm("{ .reg .u64 t; cvta.to.shared.u64 t, %1; cvt.u32.u64 %0, t; }" : "=r"(a) : "l"(p));
    return a;
}
__device__ __forceinline__ void cp16(uint32_t sa, const void* g) {
    asm volatile("cp.async.cg.shared.global [%0], [%1], 16;" :: "r"(sa), "l"(g));
}
__device__ __forceinline__ void cp_commit() { asm volatile("cp.async.commit_group;" ::: "memory"); }
__device__ __forceinline__ void cp_wait0()  { asm volatile("cp.async.wait_group 0;" ::: "memory"); }
__device__ __forceinline__ void cp_wait1()  { asm volatile("cp.async.wait_group 1;" ::: "memory"); }

__device__ __forceinline__ void ldm_x4(uint32_t& r0, uint32_t& r1, uint32_t& r2, uint32_t& r3,
                                       uint32_t a) {
    asm volatile("ldmatrix.sync.aligned.m8n8.x4.shared.b16 {%0,%1,%2,%3}, [%4];"
                 : "=r"(r0), "=r"(r1), "=r"(r2), "=r"(r3) : "r"(a));
}
__device__ __forceinline__ void mma16816(float* d, const uint32_t* a, const uint32_t* b) {
    asm volatile(
        "mma.sync.aligned.m16n8k16.row.col.f32.bf16.bf16.f32 "
        "{%0,%1,%2,%3}, {%4,%5,%6,%7}, {%8,%9}, {%0,%1,%2,%3};"
        : "+f"(d[0]), "+f"(d[1]), "+f"(d[2]), "+f"(d[3])
        : "r"(a[0]), "r"(a[1]), "r"(a[2]), "r"(a[3]), "r"(b[0]), "r"(b[1]));
}

__device__ __forceinline__ void split2(float v, bf16& h, bf16& l) {
    h = __float2bfloat16(v);
    l = __float2bfloat16(v - __bfloat162float(h));
}

// ---------------- split / embed ----------------
__global__ void split_kernel(const float* __restrict__ src,
                             bf16* __restrict__ hi, bf16* __restrict__ lo, int n4)
{
    int i = blockIdx.x * 256 + threadIdx.x;
    if (i >= n4) return;
    float4 v = reinterpret_cast<const float4*>(src)[i];
    bf16 h0, l0, h1, l1, h2, l2, h3, l3;
    split2(v.x, h0, l0); split2(v.y, h1, l1); split2(v.z, h2, l2); split2(v.w, h3, l3);
    __nv_bfloat162* H = reinterpret_cast<__nv_bfloat162*>(hi) + 2 * i;
    __nv_bfloat162* L = reinterpret_cast<__nv_bfloat162*>(lo) + 2 * i;
    H[0] = __nv_bfloat162(h0, h1); H[1] = __nv_bfloat162(h2, h3);
    L[0] = __nv_bfloat162(l0, l1); L[1] = __nv_bfloat162(l2, l3);
}

__global__ void embed_kernel(const int* __restrict__ ids,
                             const float* __restrict__ ew,
                             const float* __restrict__ pe,
                             float* __restrict__ x,
                             bf16* __restrict__ xh, bf16* __restrict__ xl)
{
    int i = blockIdx.x * 256 + threadIdx.x;
    if (i >= SS * DD) return;
    int s = i / DD, d = i - s * DD;
    float v = ew[ids[s] * DD + d] * 27.712812921102035f + pe[i];
    x[i] = v;
    bf16 h, l; split2(v, h, l);
    xh[i] = h; xl[i] = l;
}

// ---------------- HMMA GEMM: C[M,N] = A[M,K] @ B[N,K]^T (bf16x3, fp32 acc) ----------------
// 128x128 tile, BK=32, 8 warps (4M x 2N), 2-stage cp.async pipeline.
#define STG 32768
#define GEMM_SMEM (2 * STG + 128)

__global__ __launch_bounds__(256, 2)
void gemm_mma(const bf16* __restrict__ Ah, const bf16* __restrict__ Al,
              const bf16* __restrict__ Bh, const bf16* __restrict__ Bl,
              const float* __restrict__ bias,
              float* __restrict__ Cf, bf16* __restrict__ Ch, bf16* __restrict__ Cl,
              int M, int N, int K, int act)
{
    extern __shared__ char dsm[];
    uint32_t sbase = (smem_u32(dsm) + 127u) & ~127u;

    const int tid = threadIdx.x, lane = tid & 31, wid = tid >> 5;
    const int m0 = blockIdx.x * 128, n0 = blockIdx.y * 128;
    const int warp_m = (wid >> 1) * 32, warp_n = (wid & 1) * 64;

    // per-thread load slots: 8 x 16B chunks per K32 chunk
    // id = tid + t*256; tile = id>>9 (0:Ah 1:Al 2:Bh 3:Bl); idx=id&511; r=idx>>2; j=idx&3
    const bf16* gbase[8];
    uint32_t    sofs[8];
#pragma unroll
    for (int t = 0; t < 8; t++) {
        int id = tid + (t << 8);
        int tl = id >> 9;
        int idx = id & 511;
        int r = idx >> 2, j = idx & 3;
        const bf16* g;
        if      (tl == 0) g = Ah + (size_t)(m0 + r) * K;
        else if (tl == 1) g = Al + (size_t)(m0 + r) * K;
        else if (tl == 2) g = Bh + (size_t)(n0 + r) * K;
        else              g = Bl + (size_t)(n0 + r) * K;
        gbase[t] = g + j * 8;
        sofs[t]  = (uint32_t)(tl * 8192 + r * 64 + ((j ^ ((r >> 1) & 3)) << 4));
    }

    // ldmatrix fragment offsets (within stage)
    const int lr = lane & 7, lb1 = (lane >> 3) & 1, lb2 = lane >> 4;
    uint32_t aoff[2][2], boff[4][2];
#pragma unroll
    for (int mi = 0; mi < 2; mi++)
#pragma unroll
        for (int ks = 0; ks < 2; ks++) {
            int r = warp_m + mi * 16 + lr + lb1 * 8;
            int j = ks * 2 + lb2;
            aoff[mi][ks] = (uint32_t)(r * 64 + ((j ^ ((r >> 1) & 3)) << 4));
        }
#pragma unroll
    for (int nb = 0; nb < 4; nb++)
#pragma unroll
        for (int ks = 0; ks < 2; ks++) {
            int r = warp_n + nb * 16 + lr + lb2 * 8;
            int j = ks * 2 + lb1;
            boff[nb][ks] = (uint32_t)(r * 64 + ((j ^ ((r >> 1) & 3)) << 4));
        }

    float acc[2][8][4];
#pragma unroll
    for (int mi = 0; mi < 2; mi++)
#pragma unroll
        for (int ni = 0; ni < 8; ni++)
#pragma unroll
            for (int r = 0; r < 4; r++) acc[mi][ni][r] = 0.f;

    const int NC = K >> 5;

    // prologue: load chunk 0 -> stage 0
    {
        uint32_t st = sbase;
#pragma unroll
        for (int t = 0; t < 8; t++) cp16(st + sofs[t], gbase[t]);
        cp_commit();
    }

    for (int c = 0; c < NC; c++) {
        if (c + 1 < NC) {
            uint32_t st = sbase + ((c + 1) & 1) * STG;
            const int koff = (c + 1) << 5;
#pragma unroll
            for (int t = 0; t < 8; t++) cp16(st + sofs[t], gbase[t] + koff);
            cp_commit();
            cp_wait1();
        } else {
            cp_wait0();
        }
        __syncthreads();

        uint32_t st = sbase + (c & 1) * STG;
#pragma unroll
        for (int p = 0; p < 3; p++) {
            uint32_t ab = st + (p == 2 ? 8192 : 0);
            uint32_t bb = st + 16384 + (p == 1 ? 8192 : 0);
#pragma unroll
            for (int ks = 0; ks < 2; ks++) {
                uint32_t af[2][4];
                ldm_x4(af[0][0], af[0][1], af[0][2], af[0][3], ab + aoff[0][ks]);
                ldm_x4(af[1][0], af[1][1], af[1][2], af[1][3], ab + aoff[1][ks]);
#pragma unroll
                for (int nh = 0; nh < 2; nh++) {
                    uint32_t bfr[4][2];
                    ldm_x4(bfr[0][0], bfr[0][1], bfr[1][0], bfr[1][1], bb + boff[2 * nh][ks]);
                    ldm_x4(bfr[2][0], bfr[2][1], bfr[3][0], bfr[3][1], bb + boff[2 * nh + 1][ks]);
#pragma unroll
                    for (int mi = 0; mi < 2; mi++)
#pragma unroll
                        for (int nj = 0; nj < 4; nj++)
                            mma16816(acc[mi][4 * nh + nj], af[mi], bfr[nj]);
                }
            }
        }
        __syncthreads();
    }

    // epilogue
#pragma unroll
    for (int mi = 0; mi < 2; mi++) {
        int rbase = m0 + warp_m + mi * 16 + (lane >> 2);
#pragma unroll
        for (int ni = 0; ni < 8; ni++) {
            int col = n0 + warp_n + ni * 8 + (lane & 3) * 2;
            float bv0 = 0.f, bv1 = 0.f;
            if (bias) { bv0 = bias[col]; bv1 = bias[col + 1]; }
#pragma unroll
            for (int hf = 0; hf < 2; hf++) {
                int row = rbase + hf * 8;
                float v0 = acc[mi][ni][hf * 2 + 0] + bv0;
                float v1 = acc[mi][ni][hf * 2 + 1] + bv1;
                if (act) {
                    v0 = 0.5f * v0 * (1.f + erff(v0 * 0.70710678118654752f));
                    v1 = 0.5f * v1 * (1.f + erff(v1 * 0.70710678118654752f));
                }
                size_t idx = (size_t)row * N + col;
                if (Cf) { Cf[idx] = v0; Cf[idx + 1] = v1; }
                if (Ch) {
                    bf16 h0, l0, h1, l1;
                    split2(v0, h0, l0); split2(v1, h1, l1);
                    *reinterpret_cast<__nv_bfloat162*>(Ch + idx) = __nv_bfloat162(h0, h1);
                    *reinterpret_cast<__nv_bfloat162*>(Cl + idx) = __nv_bfloat162(l0, l1);
                }
            }
        }
    }
}

// ---------------- causal flash attention (SIMT, fp32) ----------------
__global__ __launch_bounds__(128)
void attn_kernel(const float* __restrict__ qkv,
                 bf16* __restrict__ oh, bf16* __restrict__ ol)
{
    __shared__ float Ks[64][64];
    __shared__ float Vs[64][64];

    const int h = blockIdx.y;
    const int tid = threadIdx.x;
    const int q_idx = blockIdx.x * 128 + tid;
    const int q_blk_end = blockIdx.x * 128 + 127;

    float q[HDIM];
    const float* qrow = qkv + (size_t)q_idx * (3 * DD) + h * HDIM;
#pragma unroll
    for (int d = 0; d < HDIM; d++) q[d] = qrow[d];

    float m = -1e30f, l = 0.f;
    float acc[HDIM];
#pragma unroll
    for (int d = 0; d < HDIM; d++) acc[d] = 0.f;

    for (int kt = 0; kt * 64 <= q_blk_end; kt++) {
#pragma unroll
        for (int r = 0; r < 8; r++) {
            int id  = tid + r * 128;
            int row = id >> 4;
            int c4  = (id & 15) << 2;
            const float* base = qkv + (size_t)(kt * 64 + row) * (3 * DD) + h * HDIM + c4;
            *reinterpret_cast<float4*>(&Ks[row][c4]) = *reinterpret_cast<const float4*>(base + DD);
            *reinterpret_cast<float4*>(&Vs[row][c4]) = *reinterpret_cast<const float4*>(base + 2 * DD);
        }
        __syncthreads();

        int jmax = q_idx - kt * 64;
        if (jmax > 63) jmax = 63;
        for (int j = 0; j <= jmax; j++) {
            float s = 0.f;
#pragma unroll
            for (int d = 0; d < HDIM; d++) s += q[d] * Ks[j][d];
            s *= 0.125f;
            float mnew = fmaxf(m, s);
            float corr = __expf(m - mnew);
            float p    = __expf(s - mnew);
            l = l * corr + p;
#pragma unroll
            for (int d = 0; d < HDIM; d++) acc[d] = acc[d] * corr + p * Vs[j][d];
            m = mnew;
        }
        __syncthreads();
    }

    float inv = 1.f / l;
    size_t ob = (size_t)q_idx * DD + h * HDIM;
#pragma unroll
    for (int d = 0; d < HDIM; d++) {
        float v = acc[d] * inv;
        bf16 hh, ll; split2(v, hh, ll);
        oh[ob + d] = hh; ol[ob + d] = ll;
    }
}

// ---------------- add + LayerNorm (+ split) ----------------
__device__ __forceinline__ float warp_sum(float v)
{
#pragma unroll
    for (int o = 16; o > 0; o >>= 1) v += __shfl_xor_sync(0xffffffffu, v, o);
    return v;
}

__global__ __launch_bounds__(256)
void add_ln_kernel(const float* __restrict__ x, const float* __restrict__ y,
                   const float* __restrict__ g, const float* __restrict__ b,
                   float* __restrict__ out,
                   bf16* __restrict__ outh, bf16* __restrict__ outl)
{
    __shared__ float buf[DD];
    __shared__ float red[8];
    const int row = blockIdx.x;
    const int tid = threadIdx.x;
    const int wid = tid >> 5, lane = tid & 31;

    float local = 0.f;
    for (int d = tid; d < DD; d += 256) {
        float v = x[(size_t)row * DD + d] + y[(size_t)row * DD + d];
        buf[d] = v;
        local += v;
    }
    local = warp_sum(local);
    if (lane == 0) red[wid] = local;
    __syncthreads();
    float tot = (lane < 8) ? red[lane] : 0.f;
    tot = warp_sum(tot);
    float mu = __shfl_sync(0xffffffffu, tot, 0) * (1.f / DD);

    float lv = 0.f;
    for (int d = tid; d < DD; d += 256) {
        float t = buf[d] - mu;
        lv += t * t;
    }
    lv = warp_sum(lv);
    __syncthreads();
    if (lane == 0) red[wid] = lv;
    __syncthreads();
    float tv = (lane < 8) ? red[lane] : 0.f;
    tv = warp_sum(tv);
    float rstd = rsqrtf(__shfl_sync(0xffffffffu, tv, 0) * (1.f / DD) + EPS);

    for (int d = tid; d < DD; d += 256) {
        float v = (buf[d] - mu) * rstd * g[d] + b[d];
        size_t idx = (size_t)row * DD + d;
        if (out) out[idx] = v;
        bf16 h, l; split2(v, h, l);
        outh[idx] = h; outl[idx] = l;
    }
}

// ---------------- launch ----------------
extern "C" void kernel_launch(void* const* d_in, const int* in_sizes, int n_in,
                              void* d_out, int out_size)
{
    const int*   ids = (const int*)  d_in[0];
    const float* ew  = (const float*)d_in[1];
    const float* pe  = (const float*)d_in[2];
    const float* inw = (const float*)d_in[3];
    const float* inb = (const float*)d_in[4];
    const float* ow  = (const float*)d_in[5];
    const float* ob  = (const float*)d_in[6];
    const float* ng  = (const float*)d_in[7];
    const float* nb  = (const float*)d_in[8];
    const float* w1  = (const float*)d_in[9];
    const float* b1  = (const float*)d_in[10];
    const float* w2  = (const float*)d_in[11];
    const float* b2  = (const float*)d_in[12];
    const float* lmw = (const float*)d_in[13];
    float* out = (float*)d_out;

    float *x, *qkv, *proj, *ln1, *f2;
    bf16 *xh, *xl, *oh, *ol, *l1h, *l1l, *f1h, *f1l, *x2h, *x2l;
    bf16 *wih, *wil, *woh, *wol, *w1h, *w1l, *w2h, *w2l, *lmh, *lml;
    cudaGetSymbolAddress((void**)&x,   g_x);
    cudaGetSymbolAddress((void**)&qkv, g_qkv);
    cudaGetSymbolAddress((void**)&proj,g_proj);
    cudaGetSymbolAddress((void**)&ln1, g_ln1);
    cudaGetSymbolAddress((void**)&f2,  g_f2);
    cudaGetSymbolAddress((void**)&xh,  g_xh);  cudaGetSymbolAddress((void**)&xl,  g_xl);
    cudaGetSymbolAddress((void**)&oh,  g_oh);  cudaGetSymbolAddress((void**)&ol,  g_ol);
    cudaGetSymbolAddress((void**)&l1h, g_l1h); cudaGetSymbolAddress((void**)&l1l, g_l1l);
    cudaGetSymbolAddress((void**)&f1h, g_f1h); cudaGetSymbolAddress((void**)&f1l, g_f1l);
    cudaGetSymbolAddress((void**)&x2h, g_x2h); cudaGetSymbolAddress((void**)&x2l, g_x2l);
    cudaGetSymbolAddress((void**)&wih, g_wih); cudaGetSymbolAddress((void**)&wil, g_wil);
    cudaGetSymbolAddress((void**)&woh, g_woh); cudaGetSymbolAddress((void**)&wol, g_wol);
    cudaGetSymbolAddress((void**)&w1h, g_w1h); cudaGetSymbolAddress((void**)&w1l, g_w1l);
    cudaGetSymbolAddress((void**)&w2h, g_w2h); cudaGetSymbolAddress((void**)&w2l, g_w2l);
    cudaGetSymbolAddress((void**)&lmh, g_lmh); cudaGetSymbolAddress((void**)&lml, g_lml);

    cudaFuncSetAttribute(gemm_mma, cudaFuncAttributeMaxDynamicSharedMemorySize, GEMM_SMEM);

    auto launch_split = [](const float* s, bf16* h, bf16* l, int n) {
        int n4 = n / 4;
        split_kernel<<<(n4 + 255) / 256, 256>>>(s, h, l, n4);
    };
    launch_split(inw, wih, wil, 3 * DD * DD);
    launch_split(ow,  woh, wol, DD * DD);
    launch_split(w1,  w1h, w1l, DFF * DD);
    launch_split(w2,  w2h, w2l, DD * DFF);
    launch_split(lmw, lmh, lml, VV * DD);

    // 1. embed (+split)
    embed_kernel<<<(SS * DD + 255) / 256, 256>>>(ids, ew, pe, x, xh, xl);

    // 2. qkv = x @ in_proj_w^T + b   [2048, 2304]
    gemm_mma<<<dim3(SS / 128, (3 * DD) / 128), 256, GEMM_SMEM>>>(
        xh, xl, wih, wil, inb, qkv, nullptr, nullptr, SS, 3 * DD, DD, 0);

    // 3. attention -> o (bf16 hi/lo)
    attn_kernel<<<dim3(SS / 128, HH), 128>>>(qkv, oh, ol);

    // 4. out proj                    [2048, 768]
    gemm_mma<<<dim3(SS / 128, DD / 128), 256, GEMM_SMEM>>>(
        oh, ol, woh, wol, ob, proj, nullptr, nullptr, SS, DD, DD, 0);

    // 5. ln1 = LN(x + proj)
    add_ln_kernel<<<SS, 256>>>(x, proj, ng, nb, ln1, l1h, l1l);

    // 6. f1 = gelu(ln1 @ w1^T + b1)  [2048, 3072] -> bf16 hi/lo
    gemm_mma<<<dim3(SS / 128, DFF / 128), 256, GEMM_SMEM>>>(
        l1h, l1l, w1h, w1l, b1, nullptr, f1h, f1l, SS, DFF, DD, 1);

    // 7. f2 = f1 @ w2^T + b2         [2048, 768]
    gemm_mma<<<dim3(SS / 128, DD / 128), 256, GEMM_SMEM>>>(
        f1h, f1l, w2h, w2l, b2, f2, nullptr, nullptr, SS, DD, DFF, 0);

    // 8. x2 = LN(ln1 + f2) -> hi/lo
    add_ln_kernel<<<SS, 256>>>(ln1, f2, ng, nb, nullptr, x2h, x2l);

    // 9. logits = x2 @ lm_head_w^T   [2048, 32000]
    gemm_mma<<<dim3(SS / 128, VV / 128), 256, GEMM_SMEM>>>(
        x2h, x2l, lmh, lml, nullptr, out, nullptr, nullptr, SS, VV, DD, 0);
}

// round 5
// speedup vs baseline: 2.3683x; 1.0546x over previous
#include <cuda_runtime.h>
#include <cuda_bf16.h>
#include <math.h>
#include <stdint.h>

// ---------------- model dims ----------------
#define DD   768
#define HH   12
#define HDIM 64
#define DFF  3072
#define VV   32000
#define SS   2048
#define EPS  1e-5f

typedef __nv_bfloat16 bf16;

// ---------------- scratch (no allocs allowed) ----------------
__device__ float g_x   [SS * DD];
__device__ float g_qkv [SS * 3 * DD];
__device__ float g_proj[SS * DD];
__device__ float g_ln1 [SS * DD];
__device__ float g_f2  [SS * DD];

__device__ bf16 g_xh [SS * DD],  g_xl [SS * DD];
__device__ bf16 g_oh [SS * DD],  g_ol [SS * DD];
__device__ bf16 g_l1h[SS * DD],  g_l1l[SS * DD];
__device__ bf16 g_f1h[SS * DFF], g_f1l[SS * DFF];
__device__ bf16 g_x2h[SS * DD],  g_x2l[SS * DD];

__device__ bf16 g_wih[3 * DD * DD], g_wil[3 * DD * DD];
__device__ bf16 g_woh[DD * DD],     g_wol[DD * DD];
__device__ bf16 g_w1h[DFF * DD],    g_w1l[DFF * DD];
__device__ bf16 g_w2h[DD * DFF],    g_w2l[DD * DFF];
__device__ bf16 g_lmh[VV * DD],     g_lml[VV * DD];

// ---------------- helpers ----------------
__device__ __forceinline__ uint32_t smem_u32(const void* p) {
    uint32_t a;
    asm("{ .reg .u64 t; cvta.to.shared.u64 t, %1; cvt.u32.u64 %0, t; }" : "=r"(a) : "l"(p));
    return a;
}
__device__ __forceinline__ void cp16(uint32_t sa, const void* g) {
    asm volatile("cp.async.cg.shared.global [%0], [%1], 16;" :: "r"(sa), "l"(g));
}
__device__ __forceinline__ void cp_commit() { asm volatile("cp.async.commit_group;" ::: "memory"); }
__device__ __forceinline__ void cp_wait0()  { asm volatile("cp.async.wait_group 0;" ::: "memory"); }
__device__ __forceinline__ void cp_wait1()  { asm volatile("cp.async.wait_group 1;" ::: "memory"); }
__device__ __forceinline__ void cp_wait2()  { asm volatile("cp.async.wait_group 2;" ::: "memory"); }

__device__ __forceinline__ void ldm_x4(uint32_t& r0, uint32_t& r1, uint32_t& r2, uint32_t& r3,
                                       uint32_t a) {
    asm volatile("ldmatrix.sync.aligned.m8n8.x4.shared.b16 {%0,%1,%2,%3}, [%4];"
                 : "=r"(r0), "=r"(r1), "=r"(r2), "=r"(r3) : "r"(a));
}
__device__ __forceinline__ void mma16816(float* d, const uint32_t* a, const uint32_t* b) {
    asm volatile(
        "mma.sync.aligned.m16n8k16.row.col.f32.bf16.bf16.f32 "
        "{%0,%1,%2,%3}, {%4,%5,%6,%7}, {%8,%9}, {%0,%1,%2,%3};"
        : "+f"(d[0]), "+f"(d[1]), "+f"(d[2]), "+f"(d[3])
        : "r"(a[0]), "r"(a[1]), "r"(a[2]), "r"(a[3]), "r"(b[0]), "r"(b[1]));
}

__device__ __forceinline__ void split2(float v, bf16& h, bf16& l) {
    h = __float2bfloat16(v);
    l = __float2bfloat16(v - __bfloat162float(h));
}

// ---------------- split / embed ----------------
__global__ void split_kernel(const float* __restrict__ src,
                             bf16* __restrict__ hi, bf16* __restrict__ lo, int n4)
{
    int i = blockIdx.x * 256 + threadIdx.x;
    if (i >= n4) return;
    float4 v = reinterpret_cast<const float4*>(src)[i];
    bf16 h0, l0, h1, l1, h2, l2, h3, l3;
    split2(v.x, h0, l0); split2(v.y, h1, l1); split2(v.z, h2, l2); split2(v.w, h3, l3);
    __nv_bfloat162* H = reinterpret_cast<__nv_bfloat162*>(hi) + 2 * i;
    __nv_bfloat162* L = reinterpret_cast<__nv_bfloat162*>(lo) + 2 * i;
    H[0] = __nv_bfloat162(h0, h1); H[1] = __nv_bfloat162(h2, h3);
    L[0] = __nv_bfloat162(l0, l1); L[1] = __nv_bfloat162(l2, l3);
}

__global__ void embed_kernel(const int* __restrict__ ids,
                             const float* __restrict__ ew,
                             const float* __restrict__ pe,
                             float* __restrict__ x,
                             bf16* __restrict__ xh, bf16* __restrict__ xl)
{
    int i = blockIdx.x * 256 + threadIdx.x;
    if (i >= SS * DD) return;
    int s = i / DD, d = i - s * DD;
    float v = ew[ids[s] * DD + d] * 27.712812921102035f + pe[i];
    x[i] = v;
    bf16 h, l; split2(v, h, l);
    xh[i] = h; xl[i] = l;
}

// ---------------- HMMA GEMM: C[M,N] = A[M,K] @ B[N,K]^T (bf16x3, fp32 acc) ----------------
// 128x128 tile, BK=32, 8 warps (4M x 2N), 3-stage cp.async pipeline,
// each smem fragment loaded ONCE per chunk (24 LDSM.x4 / warp / chunk).
#define STG 32768
#define GEMM_SMEM (3 * STG + 128)

__global__ __launch_bounds__(256, 2)
void gemm_mma(const bf16* __restrict__ Ah, const bf16* __restrict__ Al,
              const bf16* __restrict__ Bh, const bf16* __restrict__ Bl,
              const float* __restrict__ bias,
              float* __restrict__ Cf, bf16* __restrict__ Ch, bf16* __restrict__ Cl,
              int M, int N, int K, int act)
{
    extern __shared__ char dsm[];
    uint32_t sbase = (smem_u32(dsm) + 127u) & ~127u;

    const int tid = threadIdx.x, lane = tid & 31, wid = tid >> 5;
    const int m0 = blockIdx.x * 128, n0 = blockIdx.y * 128;
    const int warp_m = (wid >> 1) * 32, warp_n = (wid & 1) * 64;

    // per-thread load slots: 8 x 16B chunks per K32 chunk
    const bf16* gbase[8];
    uint32_t    sofs[8];
#pragma unroll
    for (int t = 0; t < 8; t++) {
        int id = tid + (t << 8);
        int tl = id >> 9;                    // 0:Ah 1:Al 2:Bh 3:Bl
        int idx = id & 511;
        int r = idx >> 2, j = idx & 3;
        const bf16* g;
        if      (tl == 0) g = Ah + (size_t)(m0 + r) * K;
        else if (tl == 1) g = Al + (size_t)(m0 + r) * K;
        else if (tl == 2) g = Bh + (size_t)(n0 + r) * K;
        else              g = Bl + (size_t)(n0 + r) * K;
        gbase[t] = g + j * 8;
        sofs[t]  = (uint32_t)(tl * 8192 + r * 64 + ((j ^ ((r >> 1) & 3)) << 4));
    }

    // ldmatrix fragment offsets (within stage)
    const int lr = lane & 7, lb1 = (lane >> 3) & 1, lb2 = lane >> 4;
    uint32_t aoff[2][2], boff[4][2];
#pragma unroll
    for (int mi = 0; mi < 2; mi++)
#pragma unroll
        for (int ks = 0; ks < 2; ks++) {
            int r = warp_m + mi * 16 + lr + lb1 * 8;
            int j = ks * 2 + lb2;
            aoff[mi][ks] = (uint32_t)(r * 64 + ((j ^ ((r >> 1) & 3)) << 4));
        }
#pragma unroll
    for (int nb = 0; nb < 4; nb++)
#pragma unroll
        for (int ks = 0; ks < 2; ks++) {
            int r = warp_n + nb * 16 + lr + lb2 * 8;
            int j = ks * 2 + lb1;
            boff[nb][ks] = (uint32_t)(r * 64 + ((j ^ ((r >> 1) & 3)) << 4));
        }

    float acc[2][8][4];
#pragma unroll
    for (int mi = 0; mi < 2; mi++)
#pragma unroll
        for (int ni = 0; ni < 8; ni++)
#pragma unroll
            for (int r = 0; r < 4; r++) acc[mi][ni][r] = 0.f;

    const int NC = K >> 5;

    // prologue: load chunks 0,1 -> stages 0,1
    {
        uint32_t st = sbase;
#pragma unroll
        for (int t = 0; t < 8; t++) cp16(st + sofs[t], gbase[t]);
        cp_commit();
        if (NC > 1) {
            st = sbase + STG;
#pragma unroll
            for (int t = 0; t < 8; t++) cp16(st + sofs[t], gbase[t] + 32);
            cp_commit();
        }
    }

    int stage = 0;
    for (int c = 0; c < NC; c++) {
        if (c + 2 < NC) {
            int ls = stage + 2; if (ls >= 3) ls -= 3;
            uint32_t st = sbase + ls * STG;
            const int koff = (c + 2) << 5;
#pragma unroll
            for (int t = 0; t < 8; t++) cp16(st + sofs[t], gbase[t] + koff);
            cp_commit();
            cp_wait2();
        } else if (c + 1 < NC) {
            cp_wait1();
        } else {
            cp_wait0();
        }
        __syncthreads();

        uint32_t st = sbase + stage * STG;
        const uint32_t ah_b = st, al_b = st + 8192, bh_b = st + 16384, bl_b = st + 24576;
#pragma unroll
        for (int ks = 0; ks < 2; ks++) {
            uint32_t afh[2][4], afl[2][4];
            ldm_x4(afh[0][0], afh[0][1], afh[0][2], afh[0][3], ah_b + aoff[0][ks]);
            ldm_x4(afh[1][0], afh[1][1], afh[1][2], afh[1][3], ah_b + aoff[1][ks]);
            ldm_x4(afl[0][0], afl[0][1], afl[0][2], afl[0][3], al_b + aoff[0][ks]);
            ldm_x4(afl[1][0], afl[1][1], afl[1][2], afl[1][3], al_b + aoff[1][ks]);
#pragma unroll
            for (int nh = 0; nh < 2; nh++) {
                uint32_t bh[4][2], bl[4][2];
                ldm_x4(bh[0][0], bh[0][1], bh[1][0], bh[1][1], bh_b + boff[2 * nh][ks]);
                ldm_x4(bh[2][0], bh[2][1], bh[3][0], bh[3][1], bh_b + boff[2 * nh + 1][ks]);
                ldm_x4(bl[0][0], bl[0][1], bl[1][0], bl[1][1], bl_b + boff[2 * nh][ks]);
                ldm_x4(bl[2][0], bl[2][1], bl[3][0], bl[3][1], bl_b + boff[2 * nh + 1][ks]);
#pragma unroll
                for (int mi = 0; mi < 2; mi++)
#pragma unroll
                    for (int nj = 0; nj < 4; nj++) {
                        mma16816(acc[mi][4 * nh + nj], afh[mi], bh[nj]);
                        mma16816(acc[mi][4 * nh + nj], afh[mi], bl[nj]);
                        mma16816(acc[mi][4 * nh + nj], afl[mi], bh[nj]);
                    }
            }
        }
        __syncthreads();
        stage++; if (stage >= 3) stage = 0;
    }

    // epilogue
#pragma unroll
    for (int mi = 0; mi < 2; mi++) {
        int rbase = m0 + warp_m + mi * 16 + (lane >> 2);
#pragma unroll
        for (int ni = 0; ni < 8; ni++) {
            int col = n0 + warp_n + ni * 8 + (lane & 3) * 2;
            float bv0 = 0.f, bv1 = 0.f;
            if (bias) { bv0 = bias[col]; bv1 = bias[col + 1]; }
#pragma unroll
            for (int hf = 0; hf < 2; hf++) {
                int row = rbase + hf * 8;
                float v0 = acc[mi][ni][hf * 2 + 0] + bv0;
                float v1 = acc[mi][ni][hf * 2 + 1] + bv1;
                if (act) {
                    v0 = 0.5f * v0 * (1.f + erff(v0 * 0.70710678118654752f));
                    v1 = 0.5f * v1 * (1.f + erff(v1 * 0.70710678118654752f));
                }
                size_t idx = (size_t)row * N + col;
                if (Cf) { Cf[idx] = v0; Cf[idx + 1] = v1; }
                if (Ch) {
                    bf16 h0, l0, h1, l1;
                    split2(v0, h0, l0); split2(v1, h1, l1);
                    *reinterpret_cast<__nv_bfloat162*>(Ch + idx) = __nv_bfloat162(h0, h1);
                    *reinterpret_cast<__nv_bfloat162*>(Cl + idx) = __nv_bfloat162(l0, l1);
                }
            }
        }
    }
}

// ---------------- causal flash attention (SIMT, fp32, 32-key subtiles) ----------------
__global__ __launch_bounds__(128)
void attn_kernel(const float* __restrict__ qkv,
                 bf16* __restrict__ oh, bf16* __restrict__ ol)
{
    __shared__ float Ks[64][64];
    __shared__ float Vs[64][64];

    const int h = blockIdx.y;
    const int tid = threadIdx.x;
    const int q_idx = blockIdx.x * 128 + tid;
    const int q_blk_end = blockIdx.x * 128 + 127;

    float q[HDIM];
    const float* qrow = qkv + (size_t)q_idx * (3 * DD) + h * HDIM;
#pragma unroll
    for (int d = 0; d < HDIM; d++) q[d] = qrow[d];

    float m = -1e30f, l = 0.f;
    float acc[HDIM];
#pragma unroll
    for (int d = 0; d < HDIM; d++) acc[d] = 0.f;

    for (int kt = 0; kt * 64 <= q_blk_end; kt++) {
#pragma unroll
        for (int r = 0; r < 8; r++) {
            int id  = tid + r * 128;
            int row = id >> 4;
            int c4  = (id & 15) << 2;
            const float* base = qkv + (size_t)(kt * 64 + row) * (3 * DD) + h * HDIM + c4;
            *reinterpret_cast<float4*>(&Ks[row][c4]) = *reinterpret_cast<const float4*>(base + DD);
            *reinterpret_cast<float4*>(&Vs[row][c4]) = *reinterpret_cast<const float4*>(base + 2 * DD);
        }
        __syncthreads();

#pragma unroll
        for (int sub = 0; sub < 2; sub++) {
            const int base = kt * 64 + sub * 32;
            if (base > q_idx) break;
            int jmax = q_idx - base;
            if (jmax > 31) jmax = 31;

            float s[32];
            float smax = -1e30f;
            for (int j = 0; j <= jmax; j++) {
                float acc_s = 0.f;
#pragma unroll
                for (int d = 0; d < HDIM; d++) acc_s += q[d] * Ks[sub * 32 + j][d];
                acc_s *= 0.125f;
                s[j] = acc_s;
                smax = fmaxf(smax, acc_s);
            }
            float mnew = fmaxf(m, smax);
            float corr = __expf(m - mnew);
            l *= corr;
#pragma unroll
            for (int d = 0; d < HDIM; d++) acc[d] *= corr;
            for (int j = 0; j <= jmax; j++) {
                float p = __expf(s[j] - mnew);
                l += p;
#pragma unroll
                for (int d = 0; d < HDIM; d++) acc[d] += p * Vs[sub * 32 + j][d];
            }
            m = mnew;
        }
        __syncthreads();
    }

    float inv = 1.f / l;
    size_t ob = (size_t)q_idx * DD + h * HDIM;
#pragma unroll
    for (int d = 0; d < HDIM; d++) {
        float v = acc[d] * inv;
        bf16 hh, ll; split2(v, hh, ll);
        oh[ob + d] = hh; ol[ob + d] = ll;
    }
}

// ---------------- add + LayerNorm (+ split) ----------------
__device__ __forceinline__ float warp_sum(float v)
{
#pragma unroll
    for (int o = 16; o > 0; o >>= 1) v += __shfl_xor_sync(0xffffffffu, v, o);
    return v;
}

__global__ __launch_bounds__(256)
void add_ln_kernel(const float* __restrict__ x, const float* __restrict__ y,
                   const float* __restrict__ g, const float* __restrict__ b,
                   float* __restrict__ out,
                   bf16* __restrict__ outh, bf16* __restrict__ outl)
{
    __shared__ float buf[DD];
    __shared__ float red[8];
    const int row = blockIdx.x;
    const int tid = threadIdx.x;
    const int wid = tid >> 5, lane = tid & 31;

    float local = 0.f;
    for (int d = tid; d < DD; d += 256) {
        float v = x[(size_t)row * DD + d] + y[(size_t)row * DD + d];
        buf[d] = v;
        local += v;
    }
    local = warp_sum(local);
    if (lane == 0) red[wid] = local;
    __syncthreads();
    float tot = (lane < 8) ? red[lane] : 0.f;
    tot = warp_sum(tot);
    float mu = __shfl_sync(0xffffffffu, tot, 0) * (1.f / DD);

    float lv = 0.f;
    for (int d = tid; d < DD; d += 256) {
        float t = buf[d] - mu;
        lv += t * t;
    }
    lv = warp_sum(lv);
    __syncthreads();
    if (lane == 0) red[wid] = lv;
    __syncthreads();
    float tv = (lane < 8) ? red[lane] : 0.f;
    tv = warp_sum(tv);
    float rstd = rsqrtf(__shfl_sync(0xffffffffu, tv, 0) * (1.f / DD) + EPS);

    for (int d = tid; d < DD; d += 256) {
        float v = (buf[d] - mu) * rstd * g[d] + b[d];
        size_t idx = (size_t)row * DD + d;
        if (out) out[idx] = v;
        bf16 h, l; split2(v, h, l);
        outh[idx] = h; outl[idx] = l;
    }
}

// ---------------- launch ----------------
extern "C" void kernel_launch(void* const* d_in, const int* in_sizes, int n_in,
                              void* d_out, int out_size)
{
    const int*   ids = (const int*)  d_in[0];
    const float* ew  = (const float*)d_in[1];
    const float* pe  = (const float*)d_in[2];
    const float* inw = (const float*)d_in[3];
    const float* inb = (const float*)d_in[4];
    const float* ow  = (const float*)d_in[5];
    const float* ob  = (const float*)d_in[6];
    const float* ng  = (const float*)d_in[7];
    const float* nb  = (const float*)d_in[8];
    const float* w1  = (const float*)d_in[9];
    const float* b1  = (const float*)d_in[10];
    const float* w2  = (const float*)d_in[11];
    const float* b2  = (const float*)d_in[12];
    const float* lmw = (const float*)d_in[13];
    float* out = (float*)d_out;

    float *x, *qkv, *proj, *ln1, *f2;
    bf16 *xh, *xl, *oh, *ol, *l1h, *l1l, *f1h, *f1l, *x2h, *x2l;
    bf16 *wih, *wil, *woh, *wol, *w1h, *w1l, *w2h, *w2l, *lmh, *lml;
    cudaGetSymbolAddress((void**)&x,   g_x);
    cudaGetSymbolAddress((void**)&qkv, g_qkv);
    cudaGetSymbolAddress((void**)&proj,g_proj);
    cudaGetSymbolAddress((void**)&ln1, g_ln1);
    cudaGetSymbolAddress((void**)&f2,  g_f2);
    cudaGetSymbolAddress((void**)&xh,  g_xh);  cudaGetSymbolAddress((void**)&xl,  g_xl);
    cudaGetSymbolAddress((void**)&oh,  g_oh);  cudaGetSymbolAddress((void**)&ol,  g_ol);
    cudaGetSymbolAddress((void**)&l1h, g_l1h); cudaGetSymbolAddress((void**)&l1l, g_l1l);
    cudaGetSymbolAddress((void**)&f1h, g_f1h); cudaGetSymbolAddress((void**)&f1l, g_f1l);
    cudaGetSymbolAddress((void**)&x2h, g_x2h); cudaGetSymbolAddress((void**)&x2l, g_x2l);
    cudaGetSymbolAddress((void**)&wih, g_wih); cudaGetSymbolAddress((void**)&wil, g_wil);
    cudaGetSymbolAddress((void**)&woh, g_woh); cudaGetSymbolAddress((void**)&wol, g_wol);
    cudaGetSymbolAddress((void**)&w1h, g_w1h); cudaGetSymbolAddress((void**)&w1l, g_w1l);
    cudaGetSymbolAddress((void**)&w2h, g_w2h); cudaGetSymbolAddress((void**)&w2l, g_w2l);
    cudaGetSymbolAddress((void**)&lmh, g_lmh); cudaGetSymbolAddress((void**)&lml, g_lml);

    cudaFuncSetAttribute(gemm_mma, cudaFuncAttributeMaxDynamicSharedMemorySize, GEMM_SMEM);

    auto launch_split = [](const float* s, bf16* h, bf16* l, int n) {
        int n4 = n / 4;
        split_kernel<<<(n4 + 255) / 256, 256>>>(s, h, l, n4);
    };
    launch_split(inw, wih, wil, 3 * DD * DD);
    launch_split(ow,  woh, wol, DD * DD);
    launch_split(w1,  w1h, w1l, DFF * DD);
    launch_split(w2,  w2h, w2l, DD * DFF);
    launch_split(lmw, lmh, lml, VV * DD);

    // 1. embed (+split)
    embed_kernel<<<(SS * DD + 255) / 256, 256>>>(ids, ew, pe, x, xh, xl);

    // 2. qkv = x @ in_proj_w^T + b   [2048, 2304]
    gemm_mma<<<dim3(SS / 128, (3 * DD) / 128), 256, GEMM_SMEM>>>(
        xh, xl, wih, wil, inb, qkv, nullptr, nullptr, SS, 3 * DD, DD, 0);

    // 3. attention -> o (bf16 hi/lo)
    attn_kernel<<<dim3(SS / 128, HH), 128>>>(qkv, oh, ol);

    // 4. out proj                    [2048, 768]
    gemm_mma<<<dim3(SS / 128, DD / 128), 256, GEMM_SMEM>>>(
        oh, ol, woh, wol, ob, proj, nullptr, nullptr, SS, DD, DD, 0);

    // 5. ln1 = LN(x + proj)
    add_ln_kernel<<<SS, 256>>>(x, proj, ng, nb, ln1, l1h, l1l);

    // 6. f1 = gelu(ln1 @ w1^T + b1)  [2048, 3072] -> bf16 hi/lo
    gemm_mma<<<dim3(SS / 128, DFF / 128), 256, GEMM_SMEM>>>(
        l1h, l1l, w1h, w1l, b1, nullptr, f1h, f1l, SS, DFF, DD, 1);

    // 7. f2 = f1 @ w2^T + b2         [2048, 768]
    gemm_mma<<<dim3(SS / 128, DD / 128), 256, GEMM_SMEM>>>(
        f1h, f1l, w2h, w2l, b2, f2, nullptr, nullptr, SS, DD, DFF, 0);

    // 8. x2 = LN(ln1 + f2) -> hi/lo
    add_ln_kernel<<<SS, 256>>>(ln1, f2, ng, nb, nullptr, x2h, x2l);

    // 9. logits = x2 @ lm_head_w^T   [2048, 32000]
    gemm_mma<<<dim3(SS / 128, VV / 128), 256, GEMM_SMEM>>>(
        x2h, x2l, lmh, lml, nullptr, out, nullptr, nullptr, SS, VV, DD, 0);
}

// round 6
// speedup vs baseline: 2.7489x; 1.1607x over previous
#include <cuda_runtime.h>
#include <cuda_bf16.h>
#include <cuda_fp16.h>
#include <math.h>
#include <stdint.h>

// ---------------- model dims ----------------
#define DD   768
#define HH   12
#define HDIM 64
#define DFF  3072
#define VV   32000
#define SS   2048
#define EPS  1e-5f

typedef __nv_bfloat16 bf16;

// ---------------- scratch (no allocs allowed) ----------------
__device__ float g_x   [SS * DD];
__device__ float g_qkv [SS * 3 * DD];
__device__ float g_proj[SS * DD];      // also reused as fp32 x2 (pre-LM-head)
__device__ float g_ln1 [SS * DD];
__device__ float g_f2  [SS * DD];

__device__ bf16 g_xh [SS * DD],  g_xl [SS * DD];
__device__ bf16 g_oh [SS * DD],  g_ol [SS * DD];
__device__ bf16 g_l1h[SS * DD],  g_l1l[SS * DD];
__device__ bf16 g_f1h[SS * DFF], g_f1l[SS * DFF];
__device__ bf16 g_x2h[SS * DD],  g_x2l[SS * DD];

__device__ bf16 g_wih[3 * DD * DD], g_wil[3 * DD * DD];
__device__ bf16 g_woh[DD * DD],     g_wol[DD * DD];
__device__ bf16 g_w1h[DFF * DD],    g_w1l[DFF * DD];
__device__ bf16 g_w2h[DD * DFF],    g_w2l[DD * DFF];

// fp16 path for LM head
__device__ __half g_x16h[SS * DD], g_x16l[SS * DD];
__device__ __half g_lm16[VV * DD];

// ---------------- helpers ----------------
__device__ __forceinline__ uint32_t smem_u32(const void* p) {
    uint32_t a;
    asm("{ .reg .u64 t; cvta.to.shared.u64 t, %1; cvt.u32.u64 %0, t; }" : "=r"(a) : "l"(p));
    return a;
}
__device__ __forceinline__ void cp16(uint32_t sa, const void* g) {
    asm volatile("cp.async.cg.shared.global [%0], [%1], 16;" :: "r"(sa), "l"(g));
}
__device__ __forceinline__ void cp_commit() { asm volatile("cp.async.commit_group;" ::: "memory"); }
__device__ __forceinline__ void cp_wait0()  { asm volatile("cp.async.wait_group 0;" ::: "memory"); }
__device__ __forceinline__ void cp_wait1()  { asm volatile("cp.async.wait_group 1;" ::: "memory"); }
__device__ __forceinline__ void cp_wait2()  { asm volatile("cp.async.wait_group 2;" ::: "memory"); }

__device__ __forceinline__ void ldm_x4(uint32_t& r0, uint32_t& r1, uint32_t& r2, uint32_t& r3,
                                       uint32_t a) {
    asm volatile("ldmatrix.sync.aligned.m8n8.x4.shared.b16 {%0,%1,%2,%3}, [%4];"
                 : "=r"(r0), "=r"(r1), "=r"(r2), "=r"(r3) : "r"(a));
}
__device__ __forceinline__ void mma16816(float* d, const uint32_t* a, const uint32_t* b) {
    asm volatile(
        "mma.sync.aligned.m16n8k16.row.col.f32.bf16.bf16.f32 "
        "{%0,%1,%2,%3}, {%4,%5,%6,%7}, {%8,%9}, {%0,%1,%2,%3};"
        : "+f"(d[0]), "+f"(d[1]), "+f"(d[2]), "+f"(d[3])
        : "r"(a[0]), "r"(a[1]), "r"(a[2]), "r"(a[3]), "r"(b[0]), "r"(b[1]));
}
__device__ __forceinline__ void mma16816h(float* d, const uint32_t* a, const uint32_t* b) {
    asm volatile(
        "mma.sync.aligned.m16n8k16.row.col.f32.f16.f16.f32 "
        "{%0,%1,%2,%3}, {%4,%5,%6,%7}, {%8,%9}, {%0,%1,%2,%3};"
        : "+f"(d[0]), "+f"(d[1]), "+f"(d[2]), "+f"(d[3])
        : "r"(a[0]), "r"(a[1]), "r"(a[2]), "r"(a[3]), "r"(b[0]), "r"(b[1]));
}

__device__ __forceinline__ void split2(float v, bf16& h, bf16& l) {
    h = __float2bfloat16(v);
    l = __float2bfloat16(v - __bfloat162float(h));
}
__device__ __forceinline__ void split2h(float v, __half& h, __half& l) {
    h = __float2half_rn(v);
    l = __float2half_rn(v - __half2float(h));
}

// ---------------- conversion kernels ----------------
__global__ void split_kernel(const float* __restrict__ src,
                             bf16* __restrict__ hi, bf16* __restrict__ lo, int n4)
{
    int i = blockIdx.x * 256 + threadIdx.x;
    if (i >= n4) return;
    float4 v = reinterpret_cast<const float4*>(src)[i];
    bf16 h0, l0, h1, l1, h2, l2, h3, l3;
    split2(v.x, h0, l0); split2(v.y, h1, l1); split2(v.z, h2, l2); split2(v.w, h3, l3);
    __nv_bfloat162* H = reinterpret_cast<__nv_bfloat162*>(hi) + 2 * i;
    __nv_bfloat162* L = reinterpret_cast<__nv_bfloat162*>(lo) + 2 * i;
    H[0] = __nv_bfloat162(h0, h1); H[1] = __nv_bfloat162(h2, h3);
    L[0] = __nv_bfloat162(l0, l1); L[1] = __nv_bfloat162(l2, l3);
}

__global__ void split16_kernel(const float* __restrict__ src,
                               __half* __restrict__ hi, __half* __restrict__ lo, int n4)
{
    int i = blockIdx.x * 256 + threadIdx.x;
    if (i >= n4) return;
    float4 v = reinterpret_cast<const float4*>(src)[i];
    __half h0, l0, h1, l1, h2, l2, h3, l3;
    split2h(v.x, h0, l0); split2h(v.y, h1, l1); split2h(v.z, h2, l2); split2h(v.w, h3, l3);
    __half2* H = reinterpret_cast<__half2*>(hi) + 2 * i;
    __half2* L = reinterpret_cast<__half2*>(lo) + 2 * i;
    H[0] = __half2(h0, h1); H[1] = __half2(h2, h3);
    L[0] = __half2(l0, l1); L[1] = __half2(l2, l3);
}

__global__ void cvt16_kernel(const float* __restrict__ src, __half* __restrict__ dst, int n4)
{
    int i = blockIdx.x * 256 + threadIdx.x;
    if (i >= n4) return;
    float4 v = reinterpret_cast<const float4*>(src)[i];
    __half2* D = reinterpret_cast<__half2*>(dst) + 2 * i;
    D[0] = __half2(__float2half_rn(v.x), __float2half_rn(v.y));
    D[1] = __half2(__float2half_rn(v.z), __float2half_rn(v.w));
}

__global__ void embed_kernel(const int* __restrict__ ids,
                             const float* __restrict__ ew,
                             const float* __restrict__ pe,
                             float* __restrict__ x,
                             bf16* __restrict__ xh, bf16* __restrict__ xl)
{
    int i = blockIdx.x * 256 + threadIdx.x;
    if (i >= SS * DD) return;
    int s = i / DD, d = i - s * DD;
    float v = ew[ids[s] * DD + d] * 27.712812921102035f + pe[i];
    x[i] = v;
    bf16 h, l; split2(v, h, l);
    xh[i] = h; xl[i] = l;
}

// ---------------- bf16x3 HMMA GEMM (hidden-layer GEMMs) ----------------
#define STG 32768
#define GEMM_SMEM (3 * STG + 128)

__global__ __launch_bounds__(256, 2)
void gemm_mma(const bf16* __restrict__ Ah, const bf16* __restrict__ Al,
              const bf16* __restrict__ Bh, const bf16* __restrict__ Bl,
              const float* __restrict__ bias,
              float* __restrict__ Cf, bf16* __restrict__ Ch, bf16* __restrict__ Cl,
              int M, int N, int K, int act)
{
    extern __shared__ char dsm[];
    uint32_t sbase = (smem_u32(dsm) + 127u) & ~127u;

    const int tid = threadIdx.x, lane = tid & 31, wid = tid >> 5;
    const int m0 = blockIdx.x * 128, n0 = blockIdx.y * 128;
    const int warp_m = (wid >> 1) * 32, warp_n = (wid & 1) * 64;

    const bf16* gbase[8];
    uint32_t    sofs[8];
#pragma unroll
    for (int t = 0; t < 8; t++) {
        int id = tid + (t << 8);
        int tl = id >> 9;
        int idx = id & 511;
        int r = idx >> 2, j = idx & 3;
        const bf16* g;
        if      (tl == 0) g = Ah + (size_t)(m0 + r) * K;
        else if (tl == 1) g = Al + (size_t)(m0 + r) * K;
        else if (tl == 2) g = Bh + (size_t)(n0 + r) * K;
        else              g = Bl + (size_t)(n0 + r) * K;
        gbase[t] = g + j * 8;
        sofs[t]  = (uint32_t)(tl * 8192 + r * 64 + ((j ^ ((r >> 1) & 3)) << 4));
    }

    const int lr = lane & 7, lb1 = (lane >> 3) & 1, lb2 = lane >> 4;
    uint32_t aoff[2][2], boff[4][2];
#pragma unroll
    for (int mi = 0; mi < 2; mi++)
#pragma unroll
        for (int ks = 0; ks < 2; ks++) {
            int r = warp_m + mi * 16 + lr + lb1 * 8;
            int j = ks * 2 + lb2;
            aoff[mi][ks] = (uint32_t)(r * 64 + ((j ^ ((r >> 1) & 3)) << 4));
        }
#pragma unroll
    for (int nb = 0; nb < 4; nb++)
#pragma unroll
        for (int ks = 0; ks < 2; ks++) {
            int r = warp_n + nb * 16 + lr + lb2 * 8;
            int j = ks * 2 + lb1;
            boff[nb][ks] = (uint32_t)(r * 64 + ((j ^ ((r >> 1) & 3)) << 4));
        }

    float acc[2][8][4];
#pragma unroll
    for (int mi = 0; mi < 2; mi++)
#pragma unroll
        for (int ni = 0; ni < 8; ni++)
#pragma unroll
            for (int r = 0; r < 4; r++) acc[mi][ni][r] = 0.f;

    const int NC = K >> 5;

    {
        uint32_t st = sbase;
#pragma unroll
        for (int t = 0; t < 8; t++) cp16(st + sofs[t], gbase[t]);
        cp_commit();
        if (NC > 1) {
            st = sbase + STG;
#pragma unroll
            for (int t = 0; t < 8; t++) cp16(st + sofs[t], gbase[t] + 32);
            cp_commit();
        }
    }

    int stage = 0;
    for (int c = 0; c < NC; c++) {
        if (c + 2 < NC) {
            int ls = stage + 2; if (ls >= 3) ls -= 3;
            uint32_t st = sbase + ls * STG;
            const int koff = (c + 2) << 5;
#pragma unroll
            for (int t = 0; t < 8; t++) cp16(st + sofs[t], gbase[t] + koff);
            cp_commit();
            cp_wait2();
        } else if (c + 1 < NC) {
            cp_wait1();
        } else {
            cp_wait0();
        }
        __syncthreads();

        uint32_t st = sbase + stage * STG;
        const uint32_t ah_b = st, al_b = st + 8192, bh_b = st + 16384, bl_b = st + 24576;
#pragma unroll
        for (int ks = 0; ks < 2; ks++) {
            uint32_t afh[2][4], afl[2][4];
            ldm_x4(afh[0][0], afh[0][1], afh[0][2], afh[0][3], ah_b + aoff[0][ks]);
            ldm_x4(afh[1][0], afh[1][1], afh[1][2], afh[1][3], ah_b + aoff[1][ks]);
            ldm_x4(afl[0][0], afl[0][1], afl[0][2], afl[0][3], al_b + aoff[0][ks]);
            ldm_x4(afl[1][0], afl[1][1], afl[1][2], afl[1][3], al_b + aoff[1][ks]);
#pragma unroll
            for (int nh = 0; nh < 2; nh++) {
                uint32_t bh[4][2], bl[4][2];
                ldm_x4(bh[0][0], bh[0][1], bh[1][0], bh[1][1], bh_b + boff[2 * nh][ks]);
                ldm_x4(bh[2][0], bh[2][1], bh[3][0], bh[3][1], bh_b + boff[2 * nh + 1][ks]);
                ldm_x4(bl[0][0], bl[0][1], bl[1][0], bl[1][1], bl_b + boff[2 * nh][ks]);
                ldm_x4(bl[2][0], bl[2][1], bl[3][0], bl[3][1], bl_b + boff[2 * nh + 1][ks]);
#pragma unroll
                for (int mi = 0; mi < 2; mi++)
#pragma unroll
                    for (int nj = 0; nj < 4; nj++) {
                        mma16816(acc[mi][4 * nh + nj], afh[mi], bh[nj]);
                        mma16816(acc[mi][4 * nh + nj], afh[mi], bl[nj]);
                        mma16816(acc[mi][4 * nh + nj], afl[mi], bh[nj]);
                    }
            }
        }
        __syncthreads();
        stage++; if (stage >= 3) stage = 0;
    }

#pragma unroll
    for (int mi = 0; mi < 2; mi++) {
        int rbase = m0 + warp_m + mi * 16 + (lane >> 2);
#pragma unroll
        for (int ni = 0; ni < 8; ni++) {
            int col = n0 + warp_n + ni * 8 + (lane & 3) * 2;
            float bv0 = 0.f, bv1 = 0.f;
            if (bias) { bv0 = bias[col]; bv1 = bias[col + 1]; }
#pragma unroll
            for (int hf = 0; hf < 2; hf++) {
                int row = rbase + hf * 8;
                float v0 = acc[mi][ni][hf * 2 + 0] + bv0;
                float v1 = acc[mi][ni][hf * 2 + 1] + bv1;
                if (act) {
                    v0 = 0.5f * v0 * (1.f + erff(v0 * 0.70710678118654752f));
                    v1 = 0.5f * v1 * (1.f + erff(v1 * 0.70710678118654752f));
                }
                size_t idx = (size_t)row * N + col;
                if (Cf) { Cf[idx] = v0; Cf[idx + 1] = v1; }
                if (Ch) {
                    bf16 h0, l0, h1, l1;
                    split2(v0, h0, l0); split2(v1, h1, l1);
                    *reinterpret_cast<__nv_bfloat162*>(Ch + idx) = __nv_bfloat162(h0, h1);
                    *reinterpret_cast<__nv_bfloat162*>(Cl + idx) = __nv_bfloat162(l0, l1);
                }
            }
        }
    }
}

// ---------------- LM head GEMM: C = (Ah+Al) @ Bh^T, fp16, fp32 acc ----------------
// 128x128 tile, BK=32, 8 warps, 4 stages x 24KB, lookahead 2, ONE sync per chunk.
#define LSTG 24576
#define LM_SMEM (4 * LSTG + 128)

__global__ __launch_bounds__(256, 2)
void lm_gemm(const __half* __restrict__ Ah, const __half* __restrict__ Al,
             const __half* __restrict__ Bh, float* __restrict__ Cf,
             int M, int N, int K)
{
    extern __shared__ char dsm[];
    uint32_t sbase = (smem_u32(dsm) + 127u) & ~127u;

    const int tid = threadIdx.x, lane = tid & 31, wid = tid >> 5;
    const int m0 = blockIdx.x * 128, n0 = blockIdx.y * 128;
    const int warp_m = (wid >> 1) * 32, warp_n = (wid & 1) * 64;

    // 6 x 16B loads per thread per chunk (3 tiles x 128 rows x 4 chunks = 1536)
    const __half* gbase[6];
    uint32_t      sofs[6];
#pragma unroll
    for (int t = 0; t < 6; t++) {
        int id = tid + (t << 8);
        int tl = id >> 9;                 // 0:Ah 1:Al 2:Bh
        int idx = id & 511;
        int r = idx >> 2, j = idx & 3;
        const __half* g;
        if      (tl == 0) g = Ah + (size_t)(m0 + r) * K;
        else if (tl == 1) g = Al + (size_t)(m0 + r) * K;
        else              g = Bh + (size_t)(n0 + r) * K;
        gbase[t] = g + j * 8;
        sofs[t]  = (uint32_t)(tl * 8192 + r * 64 + ((j ^ ((r >> 1) & 3)) << 4));
    }

    const int lr = lane & 7, lb1 = (lane >> 3) & 1, lb2 = lane >> 4;
    uint32_t aoff[2][2], boff[4][2];
#pragma unroll
    for (int mi = 0; mi < 2; mi++)
#pragma unroll
        for (int ks = 0; ks < 2; ks++) {
            int r = warp_m + mi * 16 + lr + lb1 * 8;
            int j = ks * 2 + lb2;
            aoff[mi][ks] = (uint32_t)(r * 64 + ((j ^ ((r >> 1) & 3)) << 4));
        }
#pragma unroll
    for (int nb = 0; nb < 4; nb++)
#pragma unroll
        for (int ks = 0; ks < 2; ks++) {
            int r = warp_n + nb * 16 + lr + lb2 * 8;
            int j = ks * 2 + lb1;
            boff[nb][ks] = (uint32_t)(r * 64 + ((j ^ ((r >> 1) & 3)) << 4));
        }

    float acc[2][8][4];
#pragma unroll
    for (int mi = 0; mi < 2; mi++)
#pragma unroll
        for (int ni = 0; ni < 8; ni++)
#pragma unroll
            for (int r = 0; r < 4; r++) acc[mi][ni][r] = 0.f;

    const int NC = K >> 5;   // 24

    // prologue: chunks 0,1 -> stages 0,1
    {
        uint32_t st = sbase;
#pragma unroll
        for (int t = 0; t < 6; t++) cp16(st + sofs[t], gbase[t]);
        cp_commit();
        st = sbase + LSTG;
#pragma unroll
        for (int t = 0; t < 6; t++) cp16(st + sofs[t], gbase[t] + 32);
        cp_commit();
    }

    for (int c = 0; c < NC; c++) {
        if (c + 2 < NC) {
            uint32_t st = sbase + ((c + 2) & 3) * LSTG;
            const int koff = (c + 2) << 5;
#pragma unroll
            for (int t = 0; t < 6; t++) cp16(st + sofs[t], gbase[t] + koff);
            cp_commit();
            cp_wait2();
        } else if (c + 1 < NC) {
            cp_wait1();
        } else {
            cp_wait0();
        }
        __syncthreads();

        uint32_t st = sbase + (c & 3) * LSTG;
        const uint32_t ah_b = st, al_b = st + 8192, bh_b = st + 16384;
#pragma unroll
        for (int ks = 0; ks < 2; ks++) {
            uint32_t afh[2][4], afl[2][4];
            ldm_x4(afh[0][0], afh[0][1], afh[0][2], afh[0][3], ah_b + aoff[0][ks]);
            ldm_x4(afh[1][0], afh[1][1], afh[1][2], afh[1][3], ah_b + aoff[1][ks]);
            ldm_x4(afl[0][0], afl[0][1], afl[0][2], afl[0][3], al_b + aoff[0][ks]);
            ldm_x4(afl[1][0], afl[1][1], afl[1][2], afl[1][3], al_b + aoff[1][ks]);
#pragma unroll
            for (int nh = 0; nh < 2; nh++) {
                uint32_t bh[4][2];
                ldm_x4(bh[0][0], bh[0][1], bh[1][0], bh[1][1], bh_b + boff[2 * nh][ks]);
                ldm_x4(bh[2][0], bh[2][1], bh[3][0], bh[3][1], bh_b + boff[2 * nh + 1][ks]);
#pragma unroll
                for (int mi = 0; mi < 2; mi++)
#pragma unroll
                    for (int nj = 0; nj < 4; nj++) {
                        mma16816h(acc[mi][4 * nh + nj], afh[mi], bh[nj]);
                        mma16816h(acc[mi][4 * nh + nj], afl[mi], bh[nj]);
                    }
            }
        }
        // no trailing sync: 4 stages + lookahead 2 keeps writes off live stages
    }

#pragma unroll
    for (int mi = 0; mi < 2; mi++) {
        int rbase = m0 + warp_m + mi * 16 + (lane >> 2);
#pragma unroll
        for (int ni = 0; ni < 8; ni++) {
            int col = n0 + warp_n + ni * 8 + (lane & 3) * 2;
#pragma unroll
            for (int hf = 0; hf < 2; hf++) {
                int row = rbase + hf * 8;
                size_t idx = (size_t)row * N + col;
                Cf[idx]     = acc[mi][ni][hf * 2 + 0];
                Cf[idx + 1] = acc[mi][ni][hf * 2 + 1];
            }
        }
    }
}

// ---------------- causal flash attention (SIMT, fp32, 32-key subtiles) ----------------
__global__ __launch_bounds__(128)
void attn_kernel(const float* __restrict__ qkv,
                 bf16* __restrict__ oh, bf16* __restrict__ ol)
{
    __shared__ float Ks[64][64];
    __shared__ float Vs[64][64];

    const int h = blockIdx.y;
    const int tid = threadIdx.x;
    const int q_idx = blockIdx.x * 128 + tid;
    const int q_blk_end = blockIdx.x * 128 + 127;

    float q[HDIM];
    const float* qrow = qkv + (size_t)q_idx * (3 * DD) + h * HDIM;
#pragma unroll
    for (int d = 0; d < HDIM; d++) q[d] = qrow[d];

    float m = -1e30f, l = 0.f;
    float acc[HDIM];
#pragma unroll
    for (int d = 0; d < HDIM; d++) acc[d] = 0.f;

    for (int kt = 0; kt * 64 <= q_blk_end; kt++) {
#pragma unroll
        for (int r = 0; r < 8; r++) {
            int id  = tid + r * 128;
            int row = id >> 4;
            int c4  = (id & 15) << 2;
            const float* base = qkv + (size_t)(kt * 64 + row) * (3 * DD) + h * HDIM + c4;
            *reinterpret_cast<float4*>(&Ks[row][c4]) = *reinterpret_cast<const float4*>(base + DD);
            *reinterpret_cast<float4*>(&Vs[row][c4]) = *reinterpret_cast<const float4*>(base + 2 * DD);
        }
        __syncthreads();

#pragma unroll
        for (int sub = 0; sub < 2; sub++) {
            const int base = kt * 64 + sub * 32;
            if (base > q_idx) break;
            int jmax = q_idx - base;
            if (jmax > 31) jmax = 31;

            float s[32];
            float smax = -1e30f;
            for (int j = 0; j <= jmax; j++) {
                float acc_s = 0.f;
#pragma unroll
                for (int d = 0; d < HDIM; d++) acc_s += q[d] * Ks[sub * 32 + j][d];
                acc_s *= 0.125f;
                s[j] = acc_s;
                smax = fmaxf(smax, acc_s);
            }
            float mnew = fmaxf(m, smax);
            float corr = __expf(m - mnew);
            l *= corr;
#pragma unroll
            for (int d = 0; d < HDIM; d++) acc[d] *= corr;
            for (int j = 0; j <= jmax; j++) {
                float p = __expf(s[j] - mnew);
                l += p;
#pragma unroll
                for (int d = 0; d < HDIM; d++) acc[d] += p * Vs[sub * 32 + j][d];
            }
            m = mnew;
        }
        __syncthreads();
    }

    float inv = 1.f / l;
    size_t ob = (size_t)q_idx * DD + h * HDIM;
#pragma unroll
    for (int d = 0; d < HDIM; d++) {
        float v = acc[d] * inv;
        bf16 hh, ll; split2(v, hh, ll);
        oh[ob + d] = hh; ol[ob + d] = ll;
    }
}

// ---------------- add + LayerNorm (+ split) ----------------
__device__ __forceinline__ float warp_sum(float v)
{
#pragma unroll
    for (int o = 16; o > 0; o >>= 1) v += __shfl_xor_sync(0xffffffffu, v, o);
    return v;
}

__global__ __launch_bounds__(256)
void add_ln_kernel(const float* __restrict__ x, const float* __restrict__ y,
                   const float* __restrict__ g, const float* __restrict__ b,
                   float* __restrict__ out,
                   bf16* __restrict__ outh, bf16* __restrict__ outl)
{
    __shared__ float buf[DD];
    __shared__ float red[8];
    const int row = blockIdx.x;
    const int tid = threadIdx.x;
    const int wid = tid >> 5, lane = tid & 31;

    float local = 0.f;
    for (int d = tid; d < DD; d += 256) {
        float v = x[(size_t)row * DD + d] + y[(size_t)row * DD + d];
        buf[d] = v;
        local += v;
    }
    local = warp_sum(local);
    if (lane == 0) red[wid] = local;
    __syncthreads();
    float tot = (lane < 8) ? red[lane] : 0.f;
    tot = warp_sum(tot);
    float mu = __shfl_sync(0xffffffffu, tot, 0) * (1.f / DD);

    float lv = 0.f;
    for (int d = tid; d < DD; d += 256) {
        float t = buf[d] - mu;
        lv += t * t;
    }
    lv = warp_sum(lv);
    __syncthreads();
    if (lane == 0) red[wid] = lv;
    __syncthreads();
    float tv = (lane < 8) ? red[lane] : 0.f;
    tv = warp_sum(tv);
    float rstd = rsqrtf(__shfl_sync(0xffffffffu, tv, 0) * (1.f / DD) + EPS);

    for (int d = tid; d < DD; d += 256) {
        float v = (buf[d] - mu) * rstd * g[d] + b[d];
        size_t idx = (size_t)row * DD + d;
        if (out) out[idx] = v;
        if (outh) {
            bf16 h, l; split2(v, h, l);
            outh[idx] = h; outl[idx] = l;
        }
    }
}

// ---------------- launch ----------------
extern "C" void kernel_launch(void* const* d_in, const int* in_sizes, int n_in,
                              void* d_out, int out_size)
{
    const int*   ids = (const int*)  d_in[0];
    const float* ew  = (const float*)d_in[1];
    const float* pe  = (const float*)d_in[2];
    const float* inw = (const float*)d_in[3];
    const float* inb = (const float*)d_in[4];
    const float* ow  = (const float*)d_in[5];
    const float* ob  = (const float*)d_in[6];
    const float* ng  = (const float*)d_in[7];
    const float* nb  = (const float*)d_in[8];
    const float* w1  = (const float*)d_in[9];
    const float* b1  = (const float*)d_in[10];
    const float* w2  = (const float*)d_in[11];
    const float* b2  = (const float*)d_in[12];
    const float* lmw = (const float*)d_in[13];
    float* out = (float*)d_out;

    float *x, *qkv, *proj, *ln1, *f2;
    bf16 *xh, *xl, *oh, *ol, *l1h, *l1l, *f1h, *f1l;
    bf16 *wih, *wil, *woh, *wol, *w1h, *w1l, *w2h, *w2l;
    __half *x16h, *x16l, *lm16;
    cudaGetSymbolAddress((void**)&x,   g_x);
    cudaGetSymbolAddress((void**)&qkv, g_qkv);
    cudaGetSymbolAddress((void**)&proj,g_proj);
    cudaGetSymbolAddress((void**)&ln1, g_ln1);
    cudaGetSymbolAddress((void**)&f2,  g_f2);
    cudaGetSymbolAddress((void**)&xh,  g_xh);  cudaGetSymbolAddress((void**)&xl,  g_xl);
    cudaGetSymbolAddress((void**)&oh,  g_oh);  cudaGetSymbolAddress((void**)&ol,  g_ol);
    cudaGetSymbolAddress((void**)&l1h, g_l1h); cudaGetSymbolAddress((void**)&l1l, g_l1l);
    cudaGetSymbolAddress((void**)&f1h, g_f1h); cudaGetSymbolAddress((void**)&f1l, g_f1l);
    cudaGetSymbolAddress((void**)&wih, g_wih); cudaGetSymbolAddress((void**)&wil, g_wil);
    cudaGetSymbolAddress((void**)&woh, g_woh); cudaGetSymbolAddress((void**)&wol, g_wol);
    cudaGetSymbolAddress((void**)&w1h, g_w1h); cudaGetSymbolAddress((void**)&w1l, g_w1l);
    cudaGetSymbolAddress((void**)&w2h, g_w2h); cudaGetSymbolAddress((void**)&w2l, g_w2l);
    cudaGetSymbolAddress((void**)&x16h, g_x16h); cudaGetSymbolAddress((void**)&x16l, g_x16l);
    cudaGetSymbolAddress((void**)&lm16, g_lm16);

    cudaFuncSetAttribute(gemm_mma, cudaFuncAttributeMaxDynamicSharedMemorySize, GEMM_SMEM);
    cudaFuncSetAttribute(lm_gemm,  cudaFuncAttributeMaxDynamicSharedMemorySize, LM_SMEM);

    auto launch_split = [](const float* s, bf16* h, bf16* l, int n) {
        int n4 = n / 4;
        split_kernel<<<(n4 + 255) / 256, 256>>>(s, h, l, n4);
    };
    launch_split(inw, wih, wil, 3 * DD * DD);
    launch_split(ow,  woh, wol, DD * DD);
    launch_split(w1,  w1h, w1l, DFF * DD);
    launch_split(w2,  w2h, w2l, DD * DFF);
    cvt16_kernel<<<(VV * DD / 4 + 255) / 256, 256>>>(lmw, lm16, VV * DD / 4);

    // 1. embed (+split)
    embed_kernel<<<(SS * DD + 255) / 256, 256>>>(ids, ew, pe, x, xh, xl);

    // 2. qkv = x @ in_proj_w^T + b   [2048, 2304]
    gemm_mma<<<dim3(SS / 128, (3 * DD) / 128), 256, GEMM_SMEM>>>(
        xh, xl, wih, wil, inb, qkv, nullptr, nullptr, SS, 3 * DD, DD, 0);

    // 3. attention -> o (bf16 hi/lo)
    attn_kernel<<<dim3(SS / 128, HH), 128>>>(qkv, oh, ol);

    // 4. out proj                    [2048, 768]
    gemm_mma<<<dim3(SS / 128, DD / 128), 256, GEMM_SMEM>>>(
        oh, ol, woh, wol, ob, proj, nullptr, nullptr, SS, DD, DD, 0);

    // 5. ln1 = LN(x + proj)
    add_ln_kernel<<<SS, 256>>>(x, proj, ng, nb, ln1, l1h, l1l);

    // 6. f1 = gelu(ln1 @ w1^T + b1)  [2048, 3072] -> bf16 hi/lo
    gemm_mma<<<dim3(SS / 128, DFF / 128), 256, GEMM_SMEM>>>(
        l1h, l1l, w1h, w1l, b1, nullptr, f1h, f1l, SS, DFF, DD, 1);

    // 7. f2 = f1 @ w2^T + b2         [2048, 768]
    gemm_mma<<<dim3(SS / 128, DD / 128), 256, GEMM_SMEM>>>(
        f1h, f1l, w2h, w2l, b2, f2, nullptr, nullptr, SS, DD, DFF, 0);

    // 8. x2 = LN(ln1 + f2) -> fp32 (reuse g_proj), then fp16 hi/lo split
    add_ln_kernel<<<SS, 256>>>(ln1, f2, ng, nb, proj, nullptr, nullptr);
    split16_kernel<<<(SS * DD / 4 + 255) / 256, 256>>>(proj, x16h, x16l, SS * DD / 4);

    // 9. logits = (x2h+x2l) @ lm16^T   [2048, 32000], fp16 2-pass
    lm_gemm<<<dim3(SS / 128, VV / 128), 256, LM_SMEM>>>(
        x16h, x16l, lm16, out, SS, VV, DD);
}

// round 11
// speedup vs baseline: 3.1157x; 1.1334x over previous
#include <cuda_runtime.h>
#include <cuda_bf16.h>
#include <cuda_fp16.h>
#include <math.h>
#include <stdint.h>

// ---------------- model dims ----------------
#define DD   768
#define HH   12
#define HDIM 64
#define DFF  3072
#define VV   32000
#define SS   2048
#define EPS  1e-5f

typedef __nv_bfloat16 bf16;

// ---------------- scratch (no allocs allowed) ----------------
__device__ float g_x   [SS * DD];
__device__ float g_qkv [SS * 3 * DD];
__device__ float g_proj[SS * DD];
__device__ float g_ln1 [SS * DD];
__device__ float g_f2  [SS * DD];

__device__ bf16 g_xh [SS * DD],  g_xl [SS * DD];
__device__ bf16 g_oh [SS * DD],  g_ol [SS * DD];
__device__ bf16 g_l1h[SS * DD],  g_l1l[SS * DD];
__device__ bf16 g_f1h[SS * DFF], g_f1l[SS * DFF];

__device__ bf16 g_wih[3 * DD * DD], g_wil[3 * DD * DD];
__device__ bf16 g_woh[DD * DD],     g_wol[DD * DD];
__device__ bf16 g_w1h[DFF * DD],    g_w1l[DFF * DD];
__device__ bf16 g_w2h[DD * DFF],    g_w2l[DD * DFF];

// fp16 path for LM head
__device__ __half g_x16 [SS * DD];
__device__ __half g_lm16[VV * DD];

// ---------------- helpers ----------------
__device__ __forceinline__ uint32_t smem_u32(const void* p) {
    uint32_t a;
    asm("{ .reg .u64 t; cvta.to.shared.u64 t, %1; cvt.u32.u64 %0, t; }" : "=r"(a) : "l"(p));
    return a;
}
__device__ __forceinline__ void cp16(uint32_t sa, const void* g) {
    asm volatile("cp.async.cg.shared.global [%0], [%1], 16;" :: "r"(sa), "l"(g));
}
__device__ __forceinline__ void cp_commit() { asm volatile("cp.async.commit_group;" ::: "memory"); }
__device__ __forceinline__ void cp_wait0()  { asm volatile("cp.async.wait_group 0;" ::: "memory"); }
__device__ __forceinline__ void cp_wait1()  { asm volatile("cp.async.wait_group 1;" ::: "memory"); }
__device__ __forceinline__ void cp_wait2()  { asm volatile("cp.async.wait_group 2;" ::: "memory"); }

__device__ __forceinline__ void ldm_x4(uint32_t& r0, uint32_t& r1, uint32_t& r2, uint32_t& r3,
                                       uint32_t a) {
    asm volatile("ldmatrix.sync.aligned.m8n8.x4.shared.b16 {%0,%1,%2,%3}, [%4];"
                 : "=r"(r0), "=r"(r1), "=r"(r2), "=r"(r3) : "r"(a));
}
__device__ __forceinline__ void mma16816(float* d, const uint32_t* a, const uint32_t* b) {
    asm volatile(
        "mma.sync.aligned.m16n8k16.row.col.f32.bf16.bf16.f32 "
        "{%0,%1,%2,%3}, {%4,%5,%6,%7}, {%8,%9}, {%0,%1,%2,%3};"
        : "+f"(d[0]), "+f"(d[1]), "+f"(d[2]), "+f"(d[3])
        : "r"(a[0]), "r"(a[1]), "r"(a[2]), "r"(a[3]), "r"(b[0]), "r"(b[1]));
}
__device__ __forceinline__ void mma16816h(float* d, const uint32_t* a, const uint32_t* b) {
    asm volatile(
        "mma.sync.aligned.m16n8k16.row.col.f32.f16.f16.f32 "
        "{%0,%1,%2,%3}, {%4,%5,%6,%7}, {%8,%9}, {%0,%1,%2,%3};"
        : "+f"(d[0]), "+f"(d[1]), "+f"(d[2]), "+f"(d[3])
        : "r"(a[0]), "r"(a[1]), "r"(a[2]), "r"(a[3]), "r"(b[0]), "r"(b[1]));
}

__device__ __forceinline__ void split2(float v, bf16& h, bf16& l) {
    h = __float2bfloat16(v);
    l = __float2bfloat16(v - __bfloat162float(h));
}

// ---------------- conversion kernels ----------------
__global__ void split_kernel(const float* __restrict__ src,
                             bf16* __restrict__ hi, bf16* __restrict__ lo, int n4)
{
    int i = blockIdx.x * 256 + threadIdx.x;
    if (i >= n4) return;
    float4 v = reinterpret_cast<const float4*>(src)[i];
    bf16 h0, l0, h1, l1, h2, l2, h3, l3;
    split2(v.x, h0, l0); split2(v.y, h1, l1); split2(v.z, h2, l2); split2(v.w, h3, l3);
    __nv_bfloat162* H = reinterpret_cast<__nv_bfloat162*>(hi) + 2 * i;
    __nv_bfloat162* L = reinterpret_cast<__nv_bfloat162*>(lo) + 2 * i;
    H[0] = __nv_bfloat162(h0, h1); H[1] = __nv_bfloat162(h2, h3);
    L[0] = __nv_bfloat162(l0, l1); L[1] = __nv_bfloat162(l2, l3);
}

__global__ void cvt16_kernel(const float* __restrict__ src, __half* __restrict__ dst, int n4)
{
    int i = blockIdx.x * 256 + threadIdx.x;
    if (i >= n4) return;
    float4 v = reinterpret_cast<const float4*>(src)[i];
    __half2* D = reinterpret_cast<__half2*>(dst) + 2 * i;
    D[0] = __half2(__float2half_rn(v.x), __float2half_rn(v.y));
    D[1] = __half2(__float2half_rn(v.z), __float2half_rn(v.w));
}

__global__ void embed_kernel(const int* __restrict__ ids,
                             const float* __restrict__ ew,
                             const float* __restrict__ pe,
                             float* __restrict__ x,
                             bf16* __restrict__ xh, bf16* __restrict__ xl)
{
    int i = blockIdx.x * 256 + threadIdx.x;
    if (i >= SS * DD) return;
    int s = i / DD, d = i - s * DD;
    float v = ew[ids[s] * DD + d] * 27.712812921102035f + pe[i];
    x[i] = v;
    bf16 h, l; split2(v, h, l);
    xh[i] = h; xl[i] = l;
}

// ---------------- bf16x3 HMMA GEMM (hidden-layer GEMMs) ----------------
#define STG 32768
#define GEMM_SMEM (3 * STG + 128)

__global__ __launch_bounds__(256, 2)
void gemm_mma(const bf16* __restrict__ Ah, const bf16* __restrict__ Al,
              const bf16* __restrict__ Bh, const bf16* __restrict__ Bl,
              const float* __restrict__ bias,
              float* __restrict__ Cf, bf16* __restrict__ Ch, bf16* __restrict__ Cl,
              int M, int N, int K, int act)
{
    extern __shared__ char dsm[];
    uint32_t sbase = (smem_u32(dsm) + 127u) & ~127u;

    const int tid = threadIdx.x, lane = tid & 31, wid = tid >> 5;
    const int m0 = blockIdx.x * 128, n0 = blockIdx.y * 128;
    const int warp_m = (wid >> 1) * 32, warp_n = (wid & 1) * 64;

    const bf16* gbase[8];
    uint32_t    sofs[8];
#pragma unroll
    for (int t = 0; t < 8; t++) {
        int id = tid + (t << 8);
        int tl = id >> 9;
        int idx = id & 511;
        int r = idx >> 2, j = idx & 3;
        const bf16* g;
        if      (tl == 0) g = Ah + (size_t)(m0 + r) * K;
        else if (tl == 1) g = Al + (size_t)(m0 + r) * K;
        else if (tl == 2) g = Bh + (size_t)(n0 + r) * K;
        else              g = Bl + (size_t)(n0 + r) * K;
        gbase[t] = g + j * 8;
        sofs[t]  = (uint32_t)(tl * 8192 + r * 64 + ((j ^ ((r >> 1) & 3)) << 4));
    }

    const int lr = lane & 7, lb1 = (lane >> 3) & 1, lb2 = lane >> 4;
    uint32_t aoff[2][2], boff[4][2];
#pragma unroll
    for (int mi = 0; mi < 2; mi++)
#pragma unroll
        for (int ks = 0; ks < 2; ks++) {
            int r = warp_m + mi * 16 + lr + lb1 * 8;
            int j = ks * 2 + lb2;
            aoff[mi][ks] = (uint32_t)(r * 64 + ((j ^ ((r >> 1) & 3)) << 4));
        }
#pragma unroll
    for (int nb = 0; nb < 4; nb++)
#pragma unroll
        for (int ks = 0; ks < 2; ks++) {
            int r = warp_n + nb * 16 + lr + lb2 * 8;
            int j = ks * 2 + lb1;
            boff[nb][ks] = (uint32_t)(r * 64 + ((j ^ ((r >> 1) & 3)) << 4));
        }

    float acc[2][8][4];
#pragma unroll
    for (int mi = 0; mi < 2; mi++)
#pragma unroll
        for (int ni = 0; ni < 8; ni++)
#pragma unroll
            for (int r = 0; r < 4; r++) acc[mi][ni][r] = 0.f;

    const int NC = K >> 5;

    {
        uint32_t st = sbase;
#pragma unroll
        for (int t = 0; t < 8; t++) cp16(st + sofs[t], gbase[t]);
        cp_commit();
        if (NC > 1) {
            st = sbase + STG;
#pragma unroll
            for (int t = 0; t < 8; t++) cp16(st + sofs[t], gbase[t] + 32);
            cp_commit();
        }
    }

    int stage = 0;
    for (int c = 0; c < NC; c++) {
        if (c + 2 < NC) {
            int ls = stage + 2; if (ls >= 3) ls -= 3;
            uint32_t st = sbase + ls * STG;
            const int koff = (c + 2) << 5;
#pragma unroll
            for (int t = 0; t < 8; t++) cp16(st + sofs[t], gbase[t] + koff);
            cp_commit();
            cp_wait2();
        } else if (c + 1 < NC) {
            cp_wait1();
        } else {
            cp_wait0();
        }
        __syncthreads();

        uint32_t st = sbase + stage * STG;
        const uint32_t ah_b = st, al_b = st + 8192, bh_b = st + 16384, bl_b = st + 24576;
#pragma unroll
        for (int ks = 0; ks < 2; ks++) {
            uint32_t afh[2][4], afl[2][4];
            ldm_x4(afh[0][0], afh[0][1], afh[0][2], afh[0][3], ah_b + aoff[0][ks]);
            ldm_x4(afh[1][0], afh[1][1], afh[1][2], afh[1][3], ah_b + aoff[1][ks]);
            ldm_x4(afl[0][0], afl[0][1], afl[0][2], afl[0][3], al_b + aoff[0][ks]);
            ldm_x4(afl[1][0], afl[1][1], afl[1][2], afl[1][3], al_b + aoff[1][ks]);
#pragma unroll
            for (int nh = 0; nh < 2; nh++) {
                uint32_t bh[4][2], bl[4][2];
                ldm_x4(bh[0][0], bh[0][1], bh[1][0], bh[1][1], bh_b + boff[2 * nh][ks]);
                ldm_x4(bh[2][0], bh[2][1], bh[3][0], bh[3][1], bh_b + boff[2 * nh + 1][ks]);
                ldm_x4(bl[0][0], bl[0][1], bl[1][0], bl[1][1], bl_b + boff[2 * nh][ks]);
                ldm_x4(bl[2][0], bl[2][1], bl[3][0], bl[3][1], bl_b + boff[2 * nh + 1][ks]);
#pragma unroll
                for (int mi = 0; mi < 2; mi++)
#pragma unroll
                    for (int nj = 0; nj < 4; nj++) {
                        mma16816(acc[mi][4 * nh + nj], afh[mi], bh[nj]);
                        mma16816(acc[mi][4 * nh + nj], afh[mi], bl[nj]);
                        mma16816(acc[mi][4 * nh + nj], afl[mi], bh[nj]);
                    }
            }
        }
        __syncthreads();
        stage++; if (stage >= 3) stage = 0;
    }

#pragma unroll
    for (int mi = 0; mi < 2; mi++) {
        int rbase = m0 + warp_m + mi * 16 + (lane >> 2);
#pragma unroll
        for (int ni = 0; ni < 8; ni++) {
            int col = n0 + warp_n + ni * 8 + (lane & 3) * 2;
            float bv0 = 0.f, bv1 = 0.f;
            if (bias) { bv0 = bias[col]; bv1 = bias[col + 1]; }
#pragma unroll
            for (int hf = 0; hf < 2; hf++) {
                int row = rbase + hf * 8;
                float v0 = acc[mi][ni][hf * 2 + 0] + bv0;
                float v1 = acc[mi][ni][hf * 2 + 1] + bv1;
                if (act) {
                    v0 = 0.5f * v0 * (1.f + erff(v0 * 0.70710678118654752f));
                    v1 = 0.5f * v1 * (1.f + erff(v1 * 0.70710678118654752f));
                }
                size_t idx = (size_t)row * N + col;
                if (Cf) { Cf[idx] = v0; Cf[idx + 1] = v1; }
                if (Ch) {
                    bf16 h0, l0, h1, l1;
                    split2(v0, h0, l0); split2(v1, h1, l1);
                    *reinterpret_cast<__nv_bfloat162*>(Ch + idx) = __nv_bfloat162(h0, h1);
                    *reinterpret_cast<__nv_bfloat162*>(Cl + idx) = __nv_bfloat162(l0, l1);
                }
            }
        }
    }
}

// ---------------- LM head GEMM: C = A @ B^T, single-pass fp16, fp32 acc ----------------
// 128x128 tile, BK=32, 8 warps, 4 stages x 16KB, lookahead 2, ONE sync per chunk.
#define LSTG 16384
#define LM_SMEM (4 * LSTG + 128)

__global__ __launch_bounds__(256, 2)
void lm_gemm(const __half* __restrict__ A, const __half* __restrict__ B,
             float* __restrict__ Cf, int M, int N, int K)
{
    extern __shared__ char dsm[];
    uint32_t sbase = (smem_u32(dsm) + 127u) & ~127u;

    const int tid = threadIdx.x, lane = tid & 31, wid = tid >> 5;
    const int m0 = blockIdx.x * 128, n0 = blockIdx.y * 128;
    const int warp_m = (wid >> 1) * 32, warp_n = (wid & 1) * 64;

    // 4 x 16B loads per thread per chunk (2 tiles x 128 rows x 4 chunks = 1024)
    const __half* gbase[4];
    uint32_t      sofs[4];
#pragma unroll
    for (int t = 0; t < 4; t++) {
        int id = tid + (t << 8);
        int tl = id >> 9;                 // 0:A 1:B
        int idx = id & 511;
        int r = idx >> 2, j = idx & 3;
        const __half* g = tl ? (B + (size_t)(n0 + r) * K) : (A + (size_t)(m0 + r) * K);
        gbase[t] = g + j * 8;
        sofs[t]  = (uint32_t)(tl * 8192 + r * 64 + ((j ^ ((r >> 1) & 3)) << 4));
    }

    const int lr = lane & 7, lb1 = (lane >> 3) & 1, lb2 = lane >> 4;
    uint32_t aoff[2][2], boff[4][2];
#pragma unroll
    for (int mi = 0; mi < 2; mi++)
#pragma unroll
        for (int ks = 0; ks < 2; ks++) {
            int r = warp_m + mi * 16 + lr + lb1 * 8;
            int j = ks * 2 + lb2;
            aoff[mi][ks] = (uint32_t)(r * 64 + ((j ^ ((r >> 1) & 3)) << 4));
        }
#pragma unroll
    for (int nb = 0; nb < 4; nb++)
#pragma unroll
        for (int ks = 0; ks < 2; ks++) {
            int r = warp_n + nb * 16 + lr + lb2 * 8;
            int j = ks * 2 + lb1;
            boff[nb][ks] = (uint32_t)(r * 64 + 8192 + ((j ^ ((r >> 1) & 3)) << 4));
        }

    float acc[2][8][4];
#pragma unroll
    for (int mi = 0; mi < 2; mi++)
#pragma unroll
        for (int ni = 0; ni < 8; ni++)
#pragma unroll
            for (int r = 0; r < 4; r++) acc[mi][ni][r] = 0.f;

    const int NC = K >> 5;   // 24

    {
        uint32_t st = sbase;
#pragma unroll
        for (int t = 0; t < 4; t++) cp16(st + sofs[t], gbase[t]);
        cp_commit();
        st = sbase + LSTG;
#pragma unroll
        for (int t = 0; t < 4; t++) cp16(st + sofs[t], gbase[t] + 32);
        cp_commit();
    }

    for (int c = 0; c < NC; c++) {
        if (c + 2 < NC) {
            uint32_t st = sbase + ((c + 2) & 3) * LSTG;
            const int koff = (c + 2) << 5;
#pragma unroll
            for (int t = 0; t < 4; t++) cp16(st + sofs[t], gbase[t] + koff);
            cp_commit();
            cp_wait2();
        } else if (c + 1 < NC) {
            cp_wait1();
        } else {
            cp_wait0();
        }
        __syncthreads();

        uint32_t st = sbase + (c & 3) * LSTG;
#pragma unroll
        for (int ks = 0; ks < 2; ks++) {
            uint32_t af[2][4];
            ldm_x4(af[0][0], af[0][1], af[0][2], af[0][3], st + aoff[0][ks]);
            ldm_x4(af[1][0], af[1][1], af[1][2], af[1][3], st + aoff[1][ks]);
#pragma unroll
            for (int nh = 0; nh < 2; nh++) {
                uint32_t bh[4][2];
                ldm_x4(bh[0][0], bh[0][1], bh[1][0], bh[1][1], st + boff[2 * nh][ks]);
                ldm_x4(bh[2][0], bh[2][1], bh[3][0], bh[3][1], st + boff[2 * nh + 1][ks]);
#pragma unroll
                for (int mi = 0; mi < 2; mi++)
#pragma unroll
                    for (int nj = 0; nj < 4; nj++)
                        mma16816h(acc[mi][4 * nh + nj], af[mi], bh[nj]);
            }
        }
        // no trailing sync: 4 stages + lookahead 2 keeps writes off live stages
    }

#pragma unroll
    for (int mi = 0; mi < 2; mi++) {
        int rbase = m0 + warp_m + mi * 16 + (lane >> 2);
#pragma unroll
        for (int ni = 0; ni < 8; ni++) {
            int col = n0 + warp_n + ni * 8 + (lane & 3) * 2;
#pragma unroll
            for (int hf = 0; hf < 2; hf++) {
                int row = rbase + hf * 8;
                size_t idx = (size_t)row * N + col;
                Cf[idx]     = acc[mi][ni][hf * 2 + 0];
                Cf[idx + 1] = acc[mi][ni][hf * 2 + 1];
            }
        }
    }
}

// ---------------- causal flash attention (SIMT, fp32, 32-key subtiles) ----------------
__global__ __launch_bounds__(128)
void attn_kernel(const float* __restrict__ qkv,
                 bf16* __restrict__ oh, bf16* __restrict__ ol)
{
    __shared__ float Ks[64][64];
    __shared__ float Vs[64][64];

    const int h = blockIdx.y;
    const int tid = threadIdx.x;
    const int q_idx = blockIdx.x * 128 + tid;
    const int q_blk_end = blockIdx.x * 128 + 127;

    float q[HDIM];
    const float* qrow = qkv + (size_t)q_idx * (3 * DD) + h * HDIM;
#pragma unroll
    for (int d = 0; d < HDIM; d++) q[d] = qrow[d];

    float m = -1e30f, l = 0.f;
    float acc[HDIM];
#pragma unroll
    for (int d = 0; d < HDIM; d++) acc[d] = 0.f;

    for (int kt = 0; kt * 64 <= q_blk_end; kt++) {
#pragma unroll
        for (int r = 0; r < 8; r++) {
            int id  = tid + r * 128;
            int row = id >> 4;
            int c4  = (id & 15) << 2;
            const float* base = qkv + (size_t)(kt * 64 + row) * (3 * DD) + h * HDIM + c4;
            *reinterpret_cast<float4*>(&Ks[row][c4]) = *reinterpret_cast<const float4*>(base + DD);
            *reinterpret_cast<float4*>(&Vs[row][c4]) = *reinterpret_cast<const float4*>(base + 2 * DD);
        }
        __syncthreads();

#pragma unroll
        for (int sub = 0; sub < 2; sub++) {
            const int base = kt * 64 + sub * 32;
            if (base > q_idx) break;
            int jmax = q_idx - base;
            if (jmax > 31) jmax = 31;

            float s[32];
            float smax = -1e30f;
            for (int j = 0; j <= jmax; j++) {
                float acc_s = 0.f;
#pragma unroll
                for (int d = 0; d < HDIM; d++) acc_s += q[d] * Ks[sub * 32 + j][d];
                acc_s *= 0.125f;
                s[j] = acc_s;
                smax = fmaxf(smax, acc_s);
            }
            float mnew = fmaxf(m, smax);
            float corr = __expf(m - mnew);
            l *= corr;
#pragma unroll
            for (int d = 0; d < HDIM; d++) acc[d] *= corr;
            for (int j = 0; j <= jmax; j++) {
                float p = __expf(s[j] - mnew);
                l += p;
#pragma unroll
                for (int d = 0; d < HDIM; d++) acc[d] += p * Vs[sub * 32 + j][d];
            }
            m = mnew;
        }
        __syncthreads();
    }

    float inv = 1.f / l;
    size_t ob = (size_t)q_idx * DD + h * HDIM;
#pragma unroll
    for (int d = 0; d < HDIM; d++) {
        float v = acc[d] * inv;
        bf16 hh, ll; split2(v, hh, ll);
        oh[ob + d] = hh; ol[ob + d] = ll;
    }
}

// ---------------- add + LayerNorm (+ bf16 split and/or fp16 out) ----------------
__device__ __forceinline__ float warp_sum(float v)
{
#pragma unroll
    for (int o = 16; o > 0; o >>= 1) v += __shfl_xor_sync(0xffffffffu, v, o);
    return v;
}

__global__ __launch_bounds__(256)
void add_ln_kernel(const float* __restrict__ x, const float* __restrict__ y,
                   const float* __restrict__ g, const float* __restrict__ b,
                   float* __restrict__ out,
                   bf16* __restrict__ outh, bf16* __restrict__ outl,
                   __half* __restrict__ out16)
{
    __shared__ float buf[DD];
    __shared__ float red[8];
    const int row = blockIdx.x;
    const int tid = threadIdx.x;
    const int wid = tid >> 5, lane = tid & 31;

    float local = 0.f;
    for (int d = tid; d < DD; d += 256) {
        float v = x[(size_t)row * DD + d] + y[(size_t)row * DD + d];
        buf[d] = v;
        local += v;
    }
    local = warp_sum(local);
    if (lane == 0) red[wid] = local;
    __syncthreads();
    float tot = (lane < 8) ? red[lane] : 0.f;
    tot = warp_sum(tot);
    float mu = __shfl_sync(0xffffffffu, tot, 0) * (1.f / DD);

    float lv = 0.f;
    for (int d = tid; d < DD; d += 256) {
        float t = buf[d] - mu;
        lv += t * t;
    }
    lv = warp_sum(lv);
    __syncthreads();
    if (lane == 0) red[wid] = lv;
    __syncthreads();
    float tv = (lane < 8) ? red[lane] : 0.f;
    tv = warp_sum(tv);
    float rstd = rsqrtf(__shfl_sync(0xffffffffu, tv, 0) * (1.f / DD) + EPS);

    for (int d = tid; d < DD; d += 256) {
        float v = (buf[d] - mu) * rstd * g[d] + b[d];
        size_t idx = (size_t)row * DD + d;
        if (out) out[idx] = v;
        if (outh) {
            bf16 h, l; split2(v, h, l);
            outh[idx] = h; outl[idx] = l;
        }
        if (out16) out16[idx] = __float2half_rn(v);
    }
}

// ---------------- launch ----------------
extern "C" void kernel_launch(void* const* d_in, const int* in_sizes, int n_in,
                              void* d_out, int out_size)
{
    const int*   ids = (const int*)  d_in[0];
    const float* ew  = (const float*)d_in[1];
    const float* pe  = (const float*)d_in[2];
    const float* inw = (const float*)d_in[3];
    const float* inb = (const float*)d_in[4];
    const float* ow  = (const float*)d_in[5];
    const float* ob  = (const float*)d_in[6];
    const float* ng  = (const float*)d_in[7];
    const float* nb  = (const float*)d_in[8];
    const float* w1  = (const float*)d_in[9];
    const float* b1  = (const float*)d_in[10];
    const float* w2  = (const float*)d_in[11];
    const float* b2  = (const float*)d_in[12];
    const float* lmw = (const float*)d_in[13];
    float* out = (float*)d_out;

    float *x, *qkv, *proj, *ln1, *f2;
    bf16 *xh, *xl, *oh, *ol, *l1h, *l1l, *f1h, *f1l;
    bf16 *wih, *wil, *woh, *wol, *w1h, *w1l, *w2h, *w2l;
    __half *x16, *lm16;
    cudaGetSymbolAddress((void**)&x,   g_x);
    cudaGetSymbolAddress((void**)&qkv, g_qkv);
    cudaGetSymbolAddress((void**)&proj,g_proj);
    cudaGetSymbolAddress((void**)&ln1, g_ln1);
    cudaGetSymbolAddress((void**)&f2,  g_f2);
    cudaGetSymbolAddress((void**)&xh,  g_xh);  cudaGetSymbolAddress((void**)&xl,  g_xl);
    cudaGetSymbolAddress((void**)&oh,  g_oh);  cudaGetSymbolAddress((void**)&ol,  g_ol);
    cudaGetSymbolAddress((void**)&l1h, g_l1h); cudaGetSymbolAddress((void**)&l1l, g_l1l);
    cudaGetSymbolAddress((void**)&f1h, g_f1h); cudaGetSymbolAddress((void**)&f1l, g_f1l);
    cudaGetSymbolAddress((void**)&wih, g_wih); cudaGetSymbolAddress((void**)&wil, g_wil);
    cudaGetSymbolAddress((void**)&woh, g_woh); cudaGetSymbolAddress((void**)&wol, g_wol);
    cudaGetSymbolAddress((void**)&w1h, g_w1h); cudaGetSymbolAddress((void**)&w1l, g_w1l);
    cudaGetSymbolAddress((void**)&w2h, g_w2h); cudaGetSymbolAddress((void**)&w2l, g_w2l);
    cudaGetSymbolAddress((void**)&x16, g_x16); cudaGetSymbolAddress((void**)&lm16, g_lm16);

    cudaFuncSetAttribute(gemm_mma, cudaFuncAttributeMaxDynamicSharedMemorySize, GEMM_SMEM);
    cudaFuncSetAttribute(lm_gemm,  cudaFuncAttributeMaxDynamicSharedMemorySize, LM_SMEM);

    auto launch_split = [](const float* s, bf16* h, bf16* l, int n) {
        int n4 = n / 4;
        split_kernel<<<(n4 + 255) / 256, 256>>>(s, h, l, n4);
    };
    launch_split(inw, wih, wil, 3 * DD * DD);
    launch_split(ow,  woh, wol, DD * DD);
    launch_split(w1,  w1h, w1l, DFF * DD);
    launch_split(w2,  w2h, w2l, DD * DFF);
    cvt16_kernel<<<(VV * DD / 4 + 255) / 256, 256>>>(lmw, lm16, VV * DD / 4);

    // 1. embed (+split)
    embed_kernel<<<(SS * DD + 255) / 256, 256>>>(ids, ew, pe, x, xh, xl);

    // 2. qkv = x @ in_proj_w^T + b   [2048, 2304]
    gemm_mma<<<dim3(SS / 128, (3 * DD) / 128), 256, GEMM_SMEM>>>(
        xh, xl, wih, wil, inb, qkv, nullptr, nullptr, SS, 3 * DD, DD, 0);

    // 3. attention -> o (bf16 hi/lo)
    attn_kernel<<<dim3(SS / 128, HH), 128>>>(qkv, oh, ol);

    // 4. out proj                    [2048, 768]
    gemm_mma<<<dim3(SS / 128, DD / 128), 256, GEMM_SMEM>>>(
        oh, ol, woh, wol, ob, proj, nullptr, nullptr, SS, DD, DD, 0);

    // 5. ln1 = LN(x + proj)
    add_ln_kernel<<<SS, 256>>>(x, proj, ng, nb, ln1, l1h, l1l, nullptr);

    // 6. f1 = gelu(ln1 @ w1^T + b1)  [2048, 3072] -> bf16 hi/lo
    gemm_mma<<<dim3(SS / 128, DFF / 128), 256, GEMM_SMEM>>>(
        l1h, l1l, w1h, w1l, b1, nullptr, f1h, f1l, SS, DFF, DD, 1);

    // 7. f2 = f1 @ w2^T + b2         [2048, 768]
    gemm_mma<<<dim3(SS / 128, DD / 128), 256, GEMM_SMEM>>>(
        f1h, f1l, w2h, w2l, b2, f2, nullptr, nullptr, SS, DD, DFF, 0);

    // 8. x2 = LN(ln1 + f2) -> fp16 directly (fused)
    add_ln_kernel<<<SS, 256>>>(ln1, f2, ng, nb, nullptr, nullptr, nullptr, x16);

    // 9. logits = x2 @ lm16^T        [2048, 32000], single-pass fp16
    lm_gemm<<<dim3(SS / 128, VV / 128), 256, LM_SMEM>>>(x16, lm16, out, SS, VV, DD);
}